// round 14
// baseline (speedup 1.0000x reference)
#include <cuda_runtime.h>
#include <cuda_fp16.h>
#include <cstdint>
#include <math.h>

#define H     768
#define BSZ   8
#define TLEN  64
#define ILEN  197
#define NHEADS 12
#define DH    64

// ---------------- device scratch (no allocations allowed) ----------------
__device__ float  g_q   [BSZ*TLEN*H];
__device__ float  g_v   [BSZ*ILEN*H];
__device__ float  g_kT  [BSZ*NHEADS*DH*ILEN];
__device__ float  g_gate[BSZ*TLEN*ILEN];
__device__ __half g_teh [BSZ*TLEN*H];   // text_emb as half (gate input)
__device__ __half g_ieh [BSZ*ILEN*H];   // image_emb as half (gate input)
__device__ __half g_WTh[6*H*H];   // W^T hi halves: Wt,Wq,Wi,Wk,Wv,W1
__device__ __half g_WTl[6*H*H];   // W^T lo residual halves

// ---------------- asm helpers (all base-sm_100-legal) ----------------
__device__ __forceinline__ uint32_t smem_u32(const void* p) {
    uint32_t a;
    asm("{ .reg .u64 t; cvta.to.shared.u64 t, %1; cvt.u32.u64 %0, t; }" : "=r"(a) : "l"(p));
    return a;
}
__device__ __forceinline__ void ldm_x4(uint32_t* r, uint32_t addr) {
    asm volatile("ldmatrix.sync.aligned.m8n8.x4.shared.b16 {%0,%1,%2,%3}, [%4];"
        : "=r"(r[0]), "=r"(r[1]), "=r"(r[2]), "=r"(r[3]) : "r"(addr));
}
__device__ __forceinline__ void ldm_x2(uint32_t* r, uint32_t addr) {
    asm volatile("ldmatrix.sync.aligned.m8n8.x2.shared.b16 {%0,%1}, [%2];"
        : "=r"(r[0]), "=r"(r[1]) : "r"(addr));
}
// fp32-accumulator mma (projections)
__device__ __forceinline__ void mma16816(float* c, const uint32_t* a, const uint32_t* b) {
    asm volatile("mma.sync.aligned.m16n8k16.row.col.f32.f16.f16.f32 "
        "{%0,%1,%2,%3}, {%4,%5,%6,%7}, {%8,%9}, {%0,%1,%2,%3};"
        : "+f"(c[0]), "+f"(c[1]), "+f"(c[2]), "+f"(c[3])
        : "r"(a[0]), "r"(a[1]), "r"(a[2]), "r"(a[3]), "r"(b[0]), "r"(b[1]));
}
// fp16-accumulator mma (gate MLP)
__device__ __forceinline__ void mma16816h(uint32_t* c, const uint32_t* a, const uint32_t* b) {
    asm volatile("mma.sync.aligned.m16n8k16.row.col.f16.f16.f16.f16 "
        "{%0,%1}, {%2,%3,%4,%5}, {%6,%7}, {%0,%1};"
        : "+r"(c[0]), "+r"(c[1])
        : "r"(a[0]), "r"(a[1]), "r"(a[2]), "r"(a[3]), "r"(b[0]), "r"(b[1]));
}
__device__ __forceinline__ uint32_t hm2(uint32_t a, uint32_t b) {
    uint32_t r; asm("mul.f16x2 %0, %1, %2;" : "=r"(r) : "r"(a), "r"(b)); return r;
}
__device__ __forceinline__ uint32_t h2bits(__half2 h) { return *reinterpret_cast<uint32_t*>(&h); }
__device__ __forceinline__ float2 h2f2(uint32_t u) {
    return __half22float2(*reinterpret_cast<__half2*>(&u));
}
#define CPA(dst, src) asm volatile("cp.async.cg.shared.global [%0], [%1], 16;" :: "r"(dst), "l"(src))
#define CPC() asm volatile("cp.async.commit_group;" ::: "memory")
#define CPW0() asm volatile("cp.async.wait_group 0;" ::: "memory")

// ---------------- prep: transpose weights, split into hi/lo halves ----------------
__global__ __launch_bounds__(256)
void prep_weights(const float* __restrict__ Wt, const float* __restrict__ Wq,
                  const float* __restrict__ Wi, const float* __restrict__ Wk,
                  const float* __restrict__ Wv, const float* __restrict__ W1) {
    __shared__ float ts[32][33];
    const float* in = (blockIdx.z == 0) ? Wt : (blockIdx.z == 1) ? Wq :
                      (blockIdx.z == 2) ? Wi : (blockIdx.z == 3) ? Wk :
                      (blockIdx.z == 4) ? Wv : W1;
    __half* oh = g_WTh + (size_t)blockIdx.z * H * H;
    __half* ol = g_WTl + (size_t)blockIdx.z * H * H;
    int x0 = blockIdx.x * 32, y0 = blockIdx.y * 32;
    int tx = threadIdx.x & 31, ty = threadIdx.x >> 5;
    #pragma unroll
    for (int j = 0; j < 32; j += 8)
        ts[ty + j][tx] = in[(y0 + ty + j) * H + x0 + tx];
    __syncthreads();
    #pragma unroll
    for (int j = 0; j < 32; j += 8) {
        float v = ts[tx][ty + j];
        __half h = __float2half_rn(v);
        __half l = __float2half_rn(v - __half2float(h));
        int o = (x0 + ty + j) * H + y0 + tx;
        oh[o] = h;
        ol[o] = l;
    }
}

// ============================================================================
// proj3: split-fp16 (3-MMA, fp32-grade) for q / k / v.
// z=0: q = text@Wq (fp32 out). z=1: k = image@Wk (scatter to kT).
// z=2: v = image@Wv (fp32 out).
// ============================================================================
#define PJ_AH 0
#define PJ_AL 32768
#define PJ_BH 65536
#define PJ_BL 98304
#define PJ_SMEM 131072

__device__ __forceinline__ void pj_fill_b2(uint32_t sb, size_t wofs,
                                           int n0, int k0, int buf, int tid) {
    int row = tid >> 1;
    int c0  = (tid & 1) * 4;
    size_t src = wofs + (size_t)(n0 + row) * H + k0;
    uint32_t dh = sb + PJ_BH + buf * 16384 + row * 128;
    uint32_t dl = sb + PJ_BL + buf * 16384 + row * 128;
    #pragma unroll
    for (int q = 0; q < 4; ++q) {
        int cidx = c0 + q;
        uint32_t sw = (uint32_t)((cidx ^ (row & 7)) << 4);
        CPA(dh + sw, g_WTh + src + cidx * 8);
        CPA(dl + sw, g_WTl + src + cidx * 8);
    }
    CPC();
}

__global__ __launch_bounds__(256)
void proj3_kernel(const float* __restrict__ text, const float* __restrict__ image,
                  const float* __restrict__ bq, const float* __restrict__ bk,
                  const float* __restrict__ bv) {
    const int z = blockIdx.z;                       // 0=q,1=k,2=v
    const int M = (z == 0) ? BSZ * TLEN : BSZ * ILEN;
    const int m0 = blockIdx.y * 128;
    if (m0 >= M) return;
    const int n0 = blockIdx.x * 128;

    const float* A = (z == 0) ? text : image;
    const size_t wofs = (size_t)((z == 0) ? 1 : (z == 1) ? 3 : 4) * H * H;
    const float* bias = (z == 0) ? bq : (z == 1) ? bk : bv;

    extern __shared__ char smem[];
    const uint32_t sb = smem_u32(smem);
    const int tid = threadIdx.x;
    const int wid = tid >> 5, lane = tid & 31;
    const int warp_m = wid & 1, warp_n = wid >> 1;

    float acc[64];
    #pragma unroll
    for (int q = 0; q < 64; ++q) acc[q] = 0.f;

    pj_fill_b2(sb, wofs, n0, 0, 0, tid);

    for (int kc = 0; kc < 12; ++kc) {
        const int buf = kc & 1;
        const int k0 = kc * 64;
        {
            int row = tid >> 1, hs = tid & 1;
            int grow = m0 + row;
            bool valid = grow < M;
            const float* src = A + (size_t)grow * H + k0 + hs * 32;
            char* ah = smem + PJ_AH + buf * 16384 + row * 128;
            char* al = smem + PJ_AL + buf * 16384 + row * 128;
            #pragma unroll
            for (int q = 0; q < 4; ++q) {
                int cidx = hs * 4 + q;
                float4 v0 = valid ? *(const float4*)(src + q * 8)
                                  : make_float4(0.f, 0.f, 0.f, 0.f);
                float4 v1 = valid ? *(const float4*)(src + q * 8 + 4)
                                  : make_float4(0.f, 0.f, 0.f, 0.f);
                float e[8] = {v0.x, v0.y, v0.z, v0.w, v1.x, v1.y, v1.z, v1.w};
                uint4 hv, lv;
                uint32_t* hp = &hv.x;
                uint32_t* lp = &lv.x;
                #pragma unroll
                for (int j = 0; j < 4; ++j) {
                    __half ha = __float2half_rn(e[2*j]);
                    __half hb = __float2half_rn(e[2*j+1]);
                    __half la = __float2half_rn(e[2*j]   - __half2float(ha));
                    __half lb = __float2half_rn(e[2*j+1] - __half2float(hb));
                    hp[j] = h2bits(__halves2half2(ha, hb));
                    lp[j] = h2bits(__halves2half2(la, lb));
                }
                uint32_t sw = (uint32_t)((cidx ^ (row & 7)) << 4);
                *(uint4*)(ah + sw) = hv;
                *(uint4*)(al + sw) = lv;
            }
        }
        CPW0();
        __syncthreads();
        if (kc < 11) pj_fill_b2(sb, wofs, n0, (kc + 1) * 64, buf ^ 1, tid);

        const uint32_t ahb = sb + PJ_AH + buf * 16384;
        const uint32_t alb = sb + PJ_AL + buf * 16384;
        const uint32_t bhb = sb + PJ_BH + buf * 16384;
        const uint32_t blb = sb + PJ_BL + buf * 16384;
        #pragma unroll
        for (int ks = 0; ks < 4; ++ks) {
            uint32_t afh[4][4], afl[4][4];
            #pragma unroll
            for (int mi = 0; mi < 4; ++mi) {
                int rowl = warp_m * 64 + mi * 16 + (lane & 15);
                int cidx = ks * 2 + (lane >> 4);
                uint32_t off = (uint32_t)(rowl * 128 + ((cidx ^ (rowl & 7)) << 4));
                ldm_x4(afh[mi], ahb + off);
                ldm_x4(afl[mi], alb + off);
            }
            uint32_t bfh[4][2], bfl[4][2];
            #pragma unroll
            for (int ni = 0; ni < 4; ++ni) {
                int nrow = warp_n * 32 + ni * 8 + (lane & 7);
                int cidx = ks * 2 + ((lane >> 3) & 1);
                uint32_t off = (uint32_t)(nrow * 128 + ((cidx ^ (nrow & 7)) << 4));
                ldm_x2(bfh[ni], bhb + off);
                ldm_x2(bfl[ni], blb + off);
            }
            #pragma unroll
            for (int mi = 0; mi < 4; ++mi)
                #pragma unroll
                for (int ni = 0; ni < 4; ++ni) {
                    float* cc = &acc[(mi * 4 + ni) * 4];
                    mma16816(cc, afh[mi], bfh[ni]);
                    mma16816(cc, afl[mi], bfh[ni]);
                    mma16816(cc, afh[mi], bfl[ni]);
                }
        }
    }

    // epilogue
    #pragma unroll
    for (int mi = 0; mi < 4; ++mi) {
        #pragma unroll
        for (int ni = 0; ni < 4; ++ni) {
            int r = m0 + warp_m * 64 + mi * 16 + (lane >> 2);
            int c = n0 + warp_n * 32 + ni * 8 + (lane & 3) * 2;
            float ba = __ldg(&bias[c]), bb = __ldg(&bias[c + 1]);
            const float* cc = &acc[(mi * 4 + ni) * 4];
            if (z == 1) {
                // k: scatter directly into kT[b][h][d][i]
                int d0 = c & (DH - 1), hh = c >> 6;
                #pragma unroll
                for (int s = 0; s < 2; ++s) {
                    int rr = r + s * 8;
                    if (rr < M) {
                        int bb2 = rr / ILEN, ii = rr - bb2 * ILEN;
                        float* base = g_kT + (((size_t)bb2 * NHEADS + hh) * DH) * ILEN + ii;
                        base[(size_t)d0 * ILEN]       = cc[s*2+0] + ba;
                        base[(size_t)(d0+1) * ILEN]   = cc[s*2+1] + bb;
                    }
                }
            } else {
                float* C = (z == 0) ? g_q : g_v;
                if (r < M)     *(float2*)(C + (size_t)r * H + c)       = make_float2(cc[0] + ba, cc[1] + bb);
                if (r + 8 < M) *(float2*)(C + (size_t)(r + 8) * H + c) = make_float2(cc[2] + ba, cc[3] + bb);
            }
        }
    }
}

// ============================================================================
// proj1: single fp16 MMA (fp16-grade is exact-equivalent for the gate path,
// which rounds te/ie to fp16 anyway). z=0: te = text@Wt -> g_teh (half).
// z=1: ie = image@Wi -> g_ieh (half).
// ============================================================================
#define P1_AH 0
#define P1_BH 32768
#define P1_SMEM 65536

__device__ __forceinline__ void p1_fill_b(uint32_t sb, size_t wofs,
                                          int n0, int k0, int buf, int tid) {
    int row = tid >> 1;
    int c0  = (tid & 1) * 4;
    size_t src = wofs + (size_t)(n0 + row) * H + k0;
    uint32_t dh = sb + P1_BH + buf * 16384 + row * 128;
    #pragma unroll
    for (int q = 0; q < 4; ++q) {
        int cidx = c0 + q;
        CPA(dh + (uint32_t)((cidx ^ (row & 7)) << 4), g_WTh + src + cidx * 8);
    }
    CPC();
}

__global__ __launch_bounds__(256)
void proj1_kernel(const float* __restrict__ text, const float* __restrict__ image,
                  const float* __restrict__ bt, const float* __restrict__ bi) {
    const int z = blockIdx.z;                       // 0=te,1=ie
    const int M = (z == 0) ? BSZ * TLEN : BSZ * ILEN;
    const int m0 = blockIdx.y * 128;
    if (m0 >= M) return;
    const int n0 = blockIdx.x * 128;

    const float* A = (z == 0) ? text : image;
    const size_t wofs = (size_t)((z == 0) ? 0 : 2) * H * H;
    const float* bias = (z == 0) ? bt : bi;
    __half* C = (z == 0) ? g_teh : g_ieh;

    extern __shared__ char smem[];
    const uint32_t sb = smem_u32(smem);
    const int tid = threadIdx.x;
    const int wid = tid >> 5, lane = tid & 31;
    const int warp_m = wid & 1, warp_n = wid >> 1;

    float acc[64];
    #pragma unroll
    for (int q = 0; q < 64; ++q) acc[q] = 0.f;

    p1_fill_b(sb, wofs, n0, 0, 0, tid);

    for (int kc = 0; kc < 12; ++kc) {
        const int buf = kc & 1;
        const int k0 = kc * 64;
        {
            int row = tid >> 1, hs = tid & 1;
            int grow = m0 + row;
            bool valid = grow < M;
            const float* src = A + (size_t)grow * H + k0 + hs * 32;
            char* ah = smem + P1_AH + buf * 16384 + row * 128;
            #pragma unroll
            for (int q = 0; q < 4; ++q) {
                int cidx = hs * 4 + q;
                float4 v0 = valid ? *(const float4*)(src + q * 8)
                                  : make_float4(0.f, 0.f, 0.f, 0.f);
                float4 v1 = valid ? *(const float4*)(src + q * 8 + 4)
                                  : make_float4(0.f, 0.f, 0.f, 0.f);
                uint4 hv;
                hv.x = h2bits(__floats2half2_rn(v0.x, v0.y));
                hv.y = h2bits(__floats2half2_rn(v0.z, v0.w));
                hv.z = h2bits(__floats2half2_rn(v1.x, v1.y));
                hv.w = h2bits(__floats2half2_rn(v1.z, v1.w));
                *(uint4*)(ah + ((cidx ^ (row & 7)) << 4)) = hv;
            }
        }
        CPW0();
        __syncthreads();
        if (kc < 11) p1_fill_b(sb, wofs, n0, (kc + 1) * 64, buf ^ 1, tid);

        const uint32_t ahb = sb + P1_AH + buf * 16384;
        const uint32_t bhb = sb + P1_BH + buf * 16384;
        #pragma unroll
        for (int ks = 0; ks < 4; ++ks) {
            uint32_t afh[4][4];
            #pragma unroll
            for (int mi = 0; mi < 4; ++mi) {
                int rowl = warp_m * 64 + mi * 16 + (lane & 15);
                int cidx = ks * 2 + (lane >> 4);
                ldm_x4(afh[mi], ahb + (uint32_t)(rowl * 128 + ((cidx ^ (rowl & 7)) << 4)));
            }
            uint32_t bfh[4][2];
            #pragma unroll
            for (int ni = 0; ni < 4; ++ni) {
                int nrow = warp_n * 32 + ni * 8 + (lane & 7);
                int cidx = ks * 2 + ((lane >> 3) & 1);
                ldm_x2(bfh[ni], bhb + (uint32_t)(nrow * 128 + ((cidx ^ (nrow & 7)) << 4)));
            }
            #pragma unroll
            for (int mi = 0; mi < 4; ++mi)
                #pragma unroll
                for (int ni = 0; ni < 4; ++ni)
                    mma16816(&acc[(mi * 4 + ni) * 4], afh[mi], bfh[ni]);
        }
    }

    #pragma unroll
    for (int mi = 0; mi < 4; ++mi) {
        #pragma unroll
        for (int ni = 0; ni < 4; ++ni) {
            int r = m0 + warp_m * 64 + mi * 16 + (lane >> 2);
            int c = n0 + warp_n * 32 + ni * 8 + (lane & 3) * 2;
            float ba = __ldg(&bias[c]), bb = __ldg(&bias[c + 1]);
            const float* cc = &acc[(mi * 4 + ni) * 4];
            if (r < M)
                *(__half2*)(C + (size_t)r * H + c) = __floats2half2_rn(cc[0] + ba, cc[1] + bb);
            if (r + 8 < M)
                *(__half2*)(C + (size_t)(r + 8) * H + c) = __floats2half2_rn(cc[2] + ba, cc[3] + bb);
        }
    }
}

// ============================================================================
// Gate kernel (R10 config — best measured 398.6us): M=256 (16t x 16i),
// N=384 per pass (2 passes), K-chunk 32. 512 thr, 16 warps 2M x 8N,
// warp tile 128x48, fp16 acc. 64B-row SMEM tiles, (c+(r>>1))&3 swizzle.
// B via cp.async double buffer. Staging now reads g_teh/g_ieh (half).
// grid (13 i-blocks, 4 t-blocks, 8 b).
// ============================================================================
#define GT_ZS   0
#define GT_B1   8192
#define GT_W2   11264
#define GT_TE   14336
#define GT_IE   39168
#define GT_A    64000
#define GT_B    96768
#define GT_SMEM 145920
#define TE_STR  776      // padded half stride

__device__ __forceinline__ void gt_fill_b(uint32_t sb, const __half* W1T,
                                          int gs, int tid) {
    const int n0 = (gs >= 24) ? 384 : 0;
    const int k0 = (gs >= 24 ? gs - 24 : gs) * 32;
    const uint32_t base = sb + GT_B + (gs & 1) * 24576;
    #pragma unroll
    for (int it = 0; it < 3; ++it) {
        int idx = tid + it * 512;          // 0..1535 (384 rows x 4 chunks)
        int r = idx >> 2, c = idx & 3;
        uint32_t dst = base + (uint32_t)(r * 64 + (((c + (r >> 1)) & 3) << 4));
        CPA(dst, W1T + (size_t)(n0 + r) * H + k0 + c * 8);
    }
    CPC();
}

__global__ __launch_bounds__(512)
void gate_kernel(const float* __restrict__ b1, const float* __restrict__ W2,
                 const float* __restrict__ b2) {
    extern __shared__ char smem[];
    const uint32_t sb = smem_u32(smem);
    const int tid = threadIdx.x;
    const int wid = tid >> 5, lane = tid & 31;
    const int warp_m = wid >> 3;        // 2 M-groups of 128 rows
    const int warp_n = wid & 7;         // 8 N-groups of 48 cols
    const int b  = blockIdx.z;
    const int t0 = blockIdx.y * 16;
    const int i0 = blockIdx.x * 16;

    float* zs  = (float*)(smem + GT_ZS);        // [8 warp_n][256 rows]
    float* b1s = (float*)(smem + GT_B1);
    float* w2s = (float*)(smem + GT_W2);
    __half* te = (__half*)(smem + GT_TE);
    __half* ie = (__half*)(smem + GT_IE);
    const __half* W1T = g_WTh + 5LL * H * H;

    // issue first B chunk immediately
    gt_fill_b(sb, W1T, 0, tid);

    for (int idx = tid; idx < 2048; idx += 512) zs[idx] = 0.f;
    for (int idx = tid; idx < H; idx += 512) { b1s[idx] = b1[idx]; w2s[idx] = W2[idx]; }

    // stage te/ie (already half in gmem; straight copy into padded stride)
    {
        const __half* teg = g_teh + ((size_t)b * TLEN + t0) * H;
        for (int u = tid; u < 16 * (H / 4); u += 512) {
            int r = u / (H / 4), c4 = (u % (H / 4)) * 4;
            *(uint2*)((char*)te + (r * TE_STR + c4) * 2) =
                *(const uint2*)(teg + r * H + c4);
        }
        const __half* ieg = g_ieh + (size_t)b * ILEN * H;
        for (int u = tid; u < 16 * (H / 4); u += 512) {
            int r = u / (H / 4), c4 = (u % (H / 4)) * 4;
            int gi = i0 + r;
            uint2 v = make_uint2(0u, 0u);
            if (gi < ILEN) v = *(const uint2*)(ieg + (size_t)gi * H + c4);
            *(uint2*)((char*)ie + (r * TE_STR + c4) * 2) = v;
        }
    }
    __syncthreads();

    for (int nc = 0; nc < 2; ++nc) {
        const int n0 = nc * 384;
        uint32_t hacc[96];                 // 8 mi x 6 ni x 2 b32
        #pragma unroll
        for (int q = 0; q < 96; ++q) hacc[q] = 0u;

        for (int kc = 0; kc < 24; ++kc) {
            const int gs = nc * 24 + kc;
            const int buf = gs & 1;
            const int k0 = kc * 32;

            // build A tile: rel = te*ie, 256 rows x 32 halves (64B rows)
            {
                char* ab = smem + GT_A + buf * 16384;
                #pragma unroll
                for (int it = 0; it < 2; ++it) {
                    int idx = tid + it * 512;     // 0..1023 (256 rows x 4 chunks)
                    int r = idx >> 2, c = idx & 3;
                    const __half* tp = te + (r >> 4) * TE_STR + k0 + c * 8;
                    const __half* ip = ie + (r & 15) * TE_STR + k0 + c * 8;
                    uint4 t4 = *(const uint4*)tp;
                    uint4 i4 = *(const uint4*)ip;
                    uint4 p;
                    p.x = hm2(t4.x, i4.x); p.y = hm2(t4.y, i4.y);
                    p.z = hm2(t4.z, i4.z); p.w = hm2(t4.w, i4.w);
                    *(uint4*)(ab + r * 64 + (((c + (r >> 1)) & 3) << 4)) = p;
                }
            }
            CPW0();
            __syncthreads();
            if (gs < 47) gt_fill_b(sb, W1T, gs + 1, tid);

            const uint32_t abase = sb + GT_A + buf * 16384;
            const uint32_t bbase = sb + GT_B + buf * 24576;
            #pragma unroll
            for (int ks = 0; ks < 2; ++ks) {
                uint32_t bf[3][4];
                #pragma unroll
                for (int nip = 0; nip < 3; ++nip) {
                    int g = lane >> 3;
                    int nrow = warp_n * 48 + nip * 16 + ((g >> 1) << 3) + (lane & 7);
                    int cidx = ks * 2 + (g & 1);
                    ldm_x4(bf[nip], bbase +
                        (uint32_t)(nrow * 64 + (((cidx + (nrow >> 1)) & 3) << 4)));
                }
                #pragma unroll
                for (int mi = 0; mi < 8; ++mi) {
                    uint32_t af[4];
                    int rowl = warp_m * 128 + mi * 16 + (lane & 15);
                    int cidx = ks * 2 + (lane >> 4);
                    ldm_x4(af, abase +
                        (uint32_t)(rowl * 64 + (((cidx + (rowl >> 1)) & 3) << 4)));
                    #pragma unroll
                    for (int nip = 0; nip < 3; ++nip) {
                        mma16816h(&hacc[(mi * 6 + nip * 2 + 0) * 2], af, &bf[nip][0]);
                        mma16816h(&hacc[(mi * 6 + nip * 2 + 1) * 2], af, &bf[nip][2]);
                    }
                }
            }
        }

        // N-pass epilogue: unpack fp16 acc, +b1, relu, dot W2 -> zs partials
        #pragma unroll
        for (int mi = 0; mi < 8; ++mi) {
            float z0 = 0.f, z1 = 0.f;
            #pragma unroll
            for (int ni = 0; ni < 6; ++ni) {
                int c = n0 + warp_n * 48 + ni * 8 + (lane & 3) * 2;
                float b1a = b1s[c], b1b = b1s[c + 1];
                float w2a = w2s[c], w2b = w2s[c + 1];
                const uint32_t* hc = &hacc[(mi * 6 + ni) * 2];
                float2 lo = h2f2(hc[0]);
                float2 hi = h2f2(hc[1]);
                z0 += fmaxf(lo.x + b1a, 0.f) * w2a + fmaxf(lo.y + b1b, 0.f) * w2b;
                z1 += fmaxf(hi.x + b1a, 0.f) * w2a + fmaxf(hi.y + b1b, 0.f) * w2b;
            }
            z0 += __shfl_xor_sync(0xffffffffu, z0, 1);
            z0 += __shfl_xor_sync(0xffffffffu, z0, 2);
            z1 += __shfl_xor_sync(0xffffffffu, z1, 1);
            z1 += __shfl_xor_sync(0xffffffffu, z1, 2);
            if ((lane & 3) == 0) {
                int r = warp_m * 128 + mi * 16 + (lane >> 2);
                zs[warp_n * 256 + r]     += z0;
                zs[warp_n * 256 + r + 8] += z1;
            }
        }
    }

    __syncthreads();
    if (tid < 256) {
        float z = b2[0];
        #pragma unroll
        for (int w = 0; w < 8; ++w) z += zs[w * 256 + tid];
        int t_l = tid >> 4, i_l = tid & 15;
        if (i0 + i_l < ILEN)
            g_gate[((size_t)b * TLEN + t0 + t_l) * ILEN + i0 + i_l] = 1.f / (1.f + expf(-z));
    }
}

// ---------------- attention: scores -> softmax -> *gate -> ctx ----------------
__global__ __launch_bounds__(256)
void attn_kernel(float* __restrict__ out) {
    __shared__ float q_s[8][DH];
    __shared__ float p_s[8][ILEN + 3];

    const int w    = threadIdx.x >> 5;
    const int lane = threadIdx.x & 31;
    const int b = blockIdx.z, h = blockIdx.y;
    const int t = blockIdx.x * 8 + w;

    const float* qrow = g_q + (b*TLEN + t)*H + h*DH;
    q_s[w][lane]      = qrow[lane];
    q_s[w][lane + 32] = qrow[lane + 32];
    __syncwarp();

    const float* kT = g_kT + (b*NHEADS + h) * DH * ILEN;
    const float scale = 0.125f;

    float mx = -1e30f;
    for (int c = 0; c < 7; ++c) {
        int i = c*32 + lane;
        float s = -1e30f;
        if (i < ILEN) {
            float a0 = 0.f, a1 = 0.f, a2 = 0.f, a3 = 0.f;
            #pragma unroll
            for (int d = 0; d < DH; d += 4) {
                a0 += q_s[w][d+0] * kT[(d+0)*ILEN + i];
                a1 += q_s[w][d+1] * kT[(d+1)*ILEN + i];
                a2 += q_s[w][d+2] * kT[(d+2)*ILEN + i];
                a3 += q_s[w][d+3] * kT[(d+3)*ILEN + i];
            }
            s = (a0 + a1 + a2 + a3) * scale;
            p_s[w][i] = s;
        }
        mx = fmaxf(mx, s);
    }
    #pragma unroll
    for (int off = 16; off; off >>= 1)
        mx = fmaxf(mx, __shfl_xor_sync(0xffffffffu, mx, off));

    float sm = 0.f;
    for (int c = 0; c < 7; ++c) {
        int i = c*32 + lane;
        if (i < ILEN) {
            float e = expf(p_s[w][i] - mx);
            p_s[w][i] = e;
            sm += e;
        }
    }
    #pragma unroll
    for (int off = 16; off; off >>= 1)
        sm += __shfl_xor_sync(0xffffffffu, sm, off);
    float inv = 1.f / sm;

    const float* gaterow = g_gate + (b*TLEN + t)*ILEN;
    for (int c = 0; c < 7; ++c) {
        int i = c*32 + lane;
        if (i < ILEN) p_s[w][i] *= inv * gaterow[i];
    }
    __syncwarp();

    float c0 = 0.f, c1 = 0.f;
    const float* vbase = g_v + b*ILEN*H + h*DH;
    for (int i = 0; i < ILEN; ++i) {
        float p = p_s[w][i];
        c0 += p * vbase[i*H + lane];
        c1 += p * vbase[i*H + lane + 32];
    }
    float* orow = out + (b*TLEN + t)*H + h*DH;
    orow[lane]      = c0;
    orow[lane + 32] = c1;
}

// ---------------- launch ----------------
extern "C" void kernel_launch(void* const* d_in, const int* in_sizes, int n_in,
                              void* d_out, int out_size) {
    const float* text  = (const float*)d_in[0];
    const float* image = (const float*)d_in[1];
    const float* Wq = (const float*)d_in[2];  const float* bq = (const float*)d_in[3];
    const float* Wk = (const float*)d_in[4];  const float* bk = (const float*)d_in[5];
    const float* Wv = (const float*)d_in[6];  const float* bv = (const float*)d_in[7];
    const float* Wt = (const float*)d_in[8];  const float* bt = (const float*)d_in[9];
    const float* Wi = (const float*)d_in[10]; const float* bi = (const float*)d_in[11];
    const float* W1 = (const float*)d_in[12]; const float* b1 = (const float*)d_in[13];
    const float* W2 = (const float*)d_in[14]; const float* b2 = (const float*)d_in[15];
    float* out = (float*)d_out;

    cudaFuncSetAttribute(proj3_kernel, cudaFuncAttributeMaxDynamicSharedMemorySize, PJ_SMEM);
    cudaFuncSetAttribute(proj1_kernel, cudaFuncAttributeMaxDynamicSharedMemorySize, P1_SMEM);
    cudaFuncSetAttribute(gate_kernel,  cudaFuncAttributeMaxDynamicSharedMemorySize, GT_SMEM);

    prep_weights<<<dim3(24, 24, 6), 256>>>(Wt, Wq, Wi, Wk, Wv, W1);
    proj1_kernel<<<dim3(6, 13, 2), 256, P1_SMEM>>>(text, image, bt, bi);
    proj3_kernel<<<dim3(6, 13, 3), 256, PJ_SMEM>>>(text, image, bq, bk, bv);
    gate_kernel<<<dim3(13, 4, 8), 512, GT_SMEM>>>(b1, W2, b2);
    attn_kernel<<<dim3(TLEN/8, NHEADS, BSZ), 256>>>(out);
}

// round 15
// speedup vs baseline: 1.0092x; 1.0092x over previous
#include <cuda_runtime.h>
#include <cuda_fp16.h>
#include <cstdint>
#include <math.h>

#define H     768
#define BSZ   8
#define TLEN  64
#define ILEN  197
#define NHEADS 12
#define DH    64

// ---------------- device scratch (no allocations allowed) ----------------
__device__ float  g_q   [BSZ*TLEN*H];
__device__ float  g_k   [BSZ*ILEN*H];
__device__ float  g_v   [BSZ*ILEN*H];
__device__ float  g_kT  [BSZ*NHEADS*DH*ILEN];
__device__ float  g_gate[BSZ*TLEN*ILEN];
__device__ __half g_teh [BSZ*TLEN*H];   // text_emb as half (gate input)
__device__ __half g_ieh [BSZ*ILEN*H];   // image_emb as half (gate input)
__device__ __half g_WTh[6*H*H];   // W^T hi halves: Wt,Wq,Wi,Wk,Wv,W1
__device__ __half g_WTl[6*H*H];   // W^T lo residual halves

// ---------------- asm helpers (all base-sm_100-legal) ----------------
__device__ __forceinline__ uint32_t smem_u32(const void* p) {
    uint32_t a;
    asm("{ .reg .u64 t; cvta.to.shared.u64 t, %1; cvt.u32.u64 %0, t; }" : "=r"(a) : "l"(p));
    return a;
}
__device__ __forceinline__ void ldm_x4(uint32_t* r, uint32_t addr) {
    asm volatile("ldmatrix.sync.aligned.m8n8.x4.shared.b16 {%0,%1,%2,%3}, [%4];"
        : "=r"(r[0]), "=r"(r[1]), "=r"(r[2]), "=r"(r[3]) : "r"(addr));
}
__device__ __forceinline__ void ldm_x2(uint32_t* r, uint32_t addr) {
    asm volatile("ldmatrix.sync.aligned.m8n8.x2.shared.b16 {%0,%1}, [%2];"
        : "=r"(r[0]), "=r"(r[1]) : "r"(addr));
}
// fp32-accumulator mma (projections)
__device__ __forceinline__ void mma16816(float* c, const uint32_t* a, const uint32_t* b) {
    asm volatile("mma.sync.aligned.m16n8k16.row.col.f32.f16.f16.f32 "
        "{%0,%1,%2,%3}, {%4,%5,%6,%7}, {%8,%9}, {%0,%1,%2,%3};"
        : "+f"(c[0]), "+f"(c[1]), "+f"(c[2]), "+f"(c[3])
        : "r"(a[0]), "r"(a[1]), "r"(a[2]), "r"(a[3]), "r"(b[0]), "r"(b[1]));
}
// fp16-accumulator mma (gate MLP)
__device__ __forceinline__ void mma16816h(uint32_t* c, const uint32_t* a, const uint32_t* b) {
    asm volatile("mma.sync.aligned.m16n8k16.row.col.f16.f16.f16.f16 "
        "{%0,%1}, {%2,%3,%4,%5}, {%6,%7}, {%0,%1};"
        : "+r"(c[0]), "+r"(c[1])
        : "r"(a[0]), "r"(a[1]), "r"(a[2]), "r"(a[3]), "r"(b[0]), "r"(b[1]));
}
__device__ __forceinline__ uint32_t hm2(uint32_t a, uint32_t b) {
    uint32_t r; asm("mul.f16x2 %0, %1, %2;" : "=r"(r) : "r"(a), "r"(b)); return r;
}
__device__ __forceinline__ uint32_t h2bits(__half2 h) { return *reinterpret_cast<uint32_t*>(&h); }
__device__ __forceinline__ float2 h2f2(uint32_t u) {
    return __half22float2(*reinterpret_cast<__half2*>(&u));
}
#define CPA(dst, src) asm volatile("cp.async.cg.shared.global [%0], [%1], 16;" :: "r"(dst), "l"(src))
#define CPC() asm volatile("cp.async.commit_group;" ::: "memory")
#define CPW0() asm volatile("cp.async.wait_group 0;" ::: "memory")

// ---------------- prep: transpose weights, split into hi/lo halves ----------------
__global__ __launch_bounds__(256)
void prep_weights(const float* __restrict__ Wt, const float* __restrict__ Wq,
                  const float* __restrict__ Wi, const float* __restrict__ Wk,
                  const float* __restrict__ Wv, const float* __restrict__ W1) {
    __shared__ float ts[32][33];
    const float* in = (blockIdx.z == 0) ? Wt : (blockIdx.z == 1) ? Wq :
                      (blockIdx.z == 2) ? Wi : (blockIdx.z == 3) ? Wk :
                      (blockIdx.z == 4) ? Wv : W1;
    __half* oh = g_WTh + (size_t)blockIdx.z * H * H;
    __half* ol = g_WTl + (size_t)blockIdx.z * H * H;
    int x0 = blockIdx.x * 32, y0 = blockIdx.y * 32;
    int tx = threadIdx.x & 31, ty = threadIdx.x >> 5;
    #pragma unroll
    for (int j = 0; j < 32; j += 8)
        ts[ty + j][tx] = in[(y0 + ty + j) * H + x0 + tx];
    __syncthreads();
    #pragma unroll
    for (int j = 0; j < 32; j += 8) {
        float v = ts[tx][ty + j];
        __half h = __float2half_rn(v);
        __half l = __float2half_rn(v - __half2float(h));
        int o = (x0 + ty + j) * H + y0 + tx;
        oh[o] = h;
        ol[o] = l;
    }
}

// ============================================================================
// proj3: split-fp16 (3-MMA, fp32-grade) for q / k / v, coalesced fp32 outputs.
// ============================================================================
#define PJ_AH 0
#define PJ_AL 32768
#define PJ_BH 65536
#define PJ_BL 98304
#define PJ_SMEM 131072

__device__ __forceinline__ void pj_fill_b2(uint32_t sb, size_t wofs,
                                           int n0, int k0, int buf, int tid) {
    int row = tid >> 1;
    int c0  = (tid & 1) * 4;
    size_t src = wofs + (size_t)(n0 + row) * H + k0;
    uint32_t dh = sb + PJ_BH + buf * 16384 + row * 128;
    uint32_t dl = sb + PJ_BL + buf * 16384 + row * 128;
    #pragma unroll
    for (int q = 0; q < 4; ++q) {
        int cidx = c0 + q;
        uint32_t sw = (uint32_t)((cidx ^ (row & 7)) << 4);
        CPA(dh + sw, g_WTh + src + cidx * 8);
        CPA(dl + sw, g_WTl + src + cidx * 8);
    }
    CPC();
}

__global__ __launch_bounds__(256)
void proj3_kernel(const float* __restrict__ text, const float* __restrict__ image,
                  const float* __restrict__ bq, const float* __restrict__ bk,
                  const float* __restrict__ bv) {
    const int z = blockIdx.z;                       // 0=q,1=k,2=v
    const int M = (z == 0) ? BSZ * TLEN : BSZ * ILEN;
    const int m0 = blockIdx.y * 128;
    if (m0 >= M) return;
    const int n0 = blockIdx.x * 128;

    const float* A = (z == 0) ? text : image;
    const size_t wofs = (size_t)((z == 0) ? 1 : (z == 1) ? 3 : 4) * H * H;
    const float* bias = (z == 0) ? bq : (z == 1) ? bk : bv;
    float* C = (z == 0) ? g_q : (z == 1) ? g_k : g_v;

    extern __shared__ char smem[];
    const uint32_t sb = smem_u32(smem);
    const int tid = threadIdx.x;
    const int wid = tid >> 5, lane = tid & 31;
    const int warp_m = wid & 1, warp_n = wid >> 1;

    float acc[64];
    #pragma unroll
    for (int q = 0; q < 64; ++q) acc[q] = 0.f;

    pj_fill_b2(sb, wofs, n0, 0, 0, tid);

    for (int kc = 0; kc < 12; ++kc) {
        const int buf = kc & 1;
        const int k0 = kc * 64;
        {
            int row = tid >> 1, hs = tid & 1;
            int grow = m0 + row;
            bool valid = grow < M;
            const float* src = A + (size_t)grow * H + k0 + hs * 32;
            char* ah = smem + PJ_AH + buf * 16384 + row * 128;
            char* al = smem + PJ_AL + buf * 16384 + row * 128;
            #pragma unroll
            for (int q = 0; q < 4; ++q) {
                int cidx = hs * 4 + q;
                float4 v0 = valid ? *(const float4*)(src + q * 8)
                                  : make_float4(0.f, 0.f, 0.f, 0.f);
                float4 v1 = valid ? *(const float4*)(src + q * 8 + 4)
                                  : make_float4(0.f, 0.f, 0.f, 0.f);
                float e[8] = {v0.x, v0.y, v0.z, v0.w, v1.x, v1.y, v1.z, v1.w};
                uint4 hv, lv;
                uint32_t* hp = &hv.x;
                uint32_t* lp = &lv.x;
                #pragma unroll
                for (int j = 0; j < 4; ++j) {
                    __half ha = __float2half_rn(e[2*j]);
                    __half hb = __float2half_rn(e[2*j+1]);
                    __half la = __float2half_rn(e[2*j]   - __half2float(ha));
                    __half lb = __float2half_rn(e[2*j+1] - __half2float(hb));
                    hp[j] = h2bits(__halves2half2(ha, hb));
                    lp[j] = h2bits(__halves2half2(la, lb));
                }
                uint32_t sw = (uint32_t)((cidx ^ (row & 7)) << 4);
                *(uint4*)(ah + sw) = hv;
                *(uint4*)(al + sw) = lv;
            }
        }
        CPW0();
        __syncthreads();
        if (kc < 11) pj_fill_b2(sb, wofs, n0, (kc + 1) * 64, buf ^ 1, tid);

        const uint32_t ahb = sb + PJ_AH + buf * 16384;
        const uint32_t alb = sb + PJ_AL + buf * 16384;
        const uint32_t bhb = sb + PJ_BH + buf * 16384;
        const uint32_t blb = sb + PJ_BL + buf * 16384;
        #pragma unroll
        for (int ks = 0; ks < 4; ++ks) {
            uint32_t afh[4][4], afl[4][4];
            #pragma unroll
            for (int mi = 0; mi < 4; ++mi) {
                int rowl = warp_m * 64 + mi * 16 + (lane & 15);
                int cidx = ks * 2 + (lane >> 4);
                uint32_t off = (uint32_t)(rowl * 128 + ((cidx ^ (rowl & 7)) << 4));
                ldm_x4(afh[mi], ahb + off);
                ldm_x4(afl[mi], alb + off);
            }
            uint32_t bfh[4][2], bfl[4][2];
            #pragma unroll
            for (int ni = 0; ni < 4; ++ni) {
                int nrow = warp_n * 32 + ni * 8 + (lane & 7);
                int cidx = ks * 2 + ((lane >> 3) & 1);
                uint32_t off = (uint32_t)(nrow * 128 + ((cidx ^ (nrow & 7)) << 4));
                ldm_x2(bfh[ni], bhb + off);
                ldm_x2(bfl[ni], blb + off);
            }
            #pragma unroll
            for (int mi = 0; mi < 4; ++mi)
                #pragma unroll
                for (int ni = 0; ni < 4; ++ni) {
                    float* cc = &acc[(mi * 4 + ni) * 4];
                    mma16816(cc, afh[mi], bfh[ni]);
                    mma16816(cc, afl[mi], bfh[ni]);
                    mma16816(cc, afh[mi], bfl[ni]);
                }
        }
    }

    #pragma unroll
    for (int mi = 0; mi < 4; ++mi) {
        #pragma unroll
        for (int ni = 0; ni < 4; ++ni) {
            int r = m0 + warp_m * 64 + mi * 16 + (lane >> 2);
            int c = n0 + warp_n * 32 + ni * 8 + (lane & 3) * 2;
            float ba = __ldg(&bias[c]), bb = __ldg(&bias[c + 1]);
            const float* cc = &acc[(mi * 4 + ni) * 4];
            if (r < M)     *(float2*)(C + (size_t)r * H + c)       = make_float2(cc[0] + ba, cc[1] + bb);
            if (r + 8 < M) *(float2*)(C + (size_t)(r + 8) * H + c) = make_float2(cc[2] + ba, cc[3] + bb);
        }
    }
}

// ============================================================================
// proj1: single fp16 MMA for te/ie (gate rounds to fp16 anyway).
// z=0: te = text@Wt -> g_teh. z=1: ie = image@Wi -> g_ieh.
// ============================================================================
#define P1_AH 0
#define P1_BH 32768
#define P1_SMEM 65536

__device__ __forceinline__ void p1_fill_b(uint32_t sb, size_t wofs,
                                          int n0, int k0, int buf, int tid) {
    int row = tid >> 1;
    int c0  = (tid & 1) * 4;
    size_t src = wofs + (size_t)(n0 + row) * H + k0;
    uint32_t dh = sb + P1_BH + buf * 16384 + row * 128;
    #pragma unroll
    for (int q = 0; q < 4; ++q) {
        int cidx = c0 + q;
        CPA(dh + (uint32_t)((cidx ^ (row & 7)) << 4), g_WTh + src + cidx * 8);
    }
    CPC();
}

__global__ __launch_bounds__(256)
void proj1_kernel(const float* __restrict__ text, const float* __restrict__ image,
                  const float* __restrict__ bt, const float* __restrict__ bi) {
    const int z = blockIdx.z;                       // 0=te,1=ie
    const int M = (z == 0) ? BSZ * TLEN : BSZ * ILEN;
    const int m0 = blockIdx.y * 128;
    if (m0 >= M) return;
    const int n0 = blockIdx.x * 128;

    const float* A = (z == 0) ? text : image;
    const size_t wofs = (size_t)((z == 0) ? 0 : 2) * H * H;
    const float* bias = (z == 0) ? bt : bi;
    __half* C = (z == 0) ? g_teh : g_ieh;

    extern __shared__ char smem[];
    const uint32_t sb = smem_u32(smem);
    const int tid = threadIdx.x;
    const int wid = tid >> 5, lane = tid & 31;
    const int warp_m = wid & 1, warp_n = wid >> 1;

    float acc[64];
    #pragma unroll
    for (int q = 0; q < 64; ++q) acc[q] = 0.f;

    p1_fill_b(sb, wofs, n0, 0, 0, tid);

    for (int kc = 0; kc < 12; ++kc) {
        const int buf = kc & 1;
        const int k0 = kc * 64;
        {
            int row = tid >> 1, hs = tid & 1;
            int grow = m0 + row;
            bool valid = grow < M;
            const float* src = A + (size_t)grow * H + k0 + hs * 32;
            char* ah = smem + P1_AH + buf * 16384 + row * 128;
            #pragma unroll
            for (int q = 0; q < 4; ++q) {
                int cidx = hs * 4 + q;
                float4 v0 = valid ? *(const float4*)(src + q * 8)
                                  : make_float4(0.f, 0.f, 0.f, 0.f);
                float4 v1 = valid ? *(const float4*)(src + q * 8 + 4)
                                  : make_float4(0.f, 0.f, 0.f, 0.f);
                uint4 hv;
                hv.x = h2bits(__floats2half2_rn(v0.x, v0.y));
                hv.y = h2bits(__floats2half2_rn(v0.z, v0.w));
                hv.z = h2bits(__floats2half2_rn(v1.x, v1.y));
                hv.w = h2bits(__floats2half2_rn(v1.z, v1.w));
                *(uint4*)(ah + ((cidx ^ (row & 7)) << 4)) = hv;
            }
        }
        CPW0();
        __syncthreads();
        if (kc < 11) p1_fill_b(sb, wofs, n0, (kc + 1) * 64, buf ^ 1, tid);

        const uint32_t ahb = sb + P1_AH + buf * 16384;
        const uint32_t bhb = sb + P1_BH + buf * 16384;
        #pragma unroll
        for (int ks = 0; ks < 4; ++ks) {
            uint32_t afh[4][4];
            #pragma unroll
            for (int mi = 0; mi < 4; ++mi) {
                int rowl = warp_m * 64 + mi * 16 + (lane & 15);
                int cidx = ks * 2 + (lane >> 4);
                ldm_x4(afh[mi], ahb + (uint32_t)(rowl * 128 + ((cidx ^ (rowl & 7)) << 4)));
            }
            uint32_t bfh[4][2];
            #pragma unroll
            for (int ni = 0; ni < 4; ++ni) {
                int nrow = warp_n * 32 + ni * 8 + (lane & 7);
                int cidx = ks * 2 + ((lane >> 3) & 1);
                ldm_x2(bfh[ni], bhb + (uint32_t)(nrow * 128 + ((cidx ^ (nrow & 7)) << 4)));
            }
            #pragma unroll
            for (int mi = 0; mi < 4; ++mi)
                #pragma unroll
                for (int ni = 0; ni < 4; ++ni)
                    mma16816(&acc[(mi * 4 + ni) * 4], afh[mi], bfh[ni]);
        }
    }

    #pragma unroll
    for (int mi = 0; mi < 4; ++mi) {
        #pragma unroll
        for (int ni = 0; ni < 4; ++ni) {
            int r = m0 + warp_m * 64 + mi * 16 + (lane >> 2);
            int c = n0 + warp_n * 32 + ni * 8 + (lane & 3) * 2;
            float ba = __ldg(&bias[c]), bb = __ldg(&bias[c + 1]);
            const float* cc = &acc[(mi * 4 + ni) * 4];
            if (r < M)
                *(__half2*)(C + (size_t)r * H + c) = __floats2half2_rn(cc[0] + ba, cc[1] + bb);
            if (r + 8 < M)
                *(__half2*)(C + (size_t)(r + 8) * H + c) = __floats2half2_rn(cc[2] + ba, cc[3] + bb);
        }
    }
}

// ============================================================================
// Gate kernel (R10 config — best measured 398.6us): M=256 (16t x 16i),
// N=384 per pass (2 passes), K-chunk 32. 512 thr, 16 warps 2M x 8N,
// warp tile 128x48, fp16 acc. 64B-row SMEM tiles, (c+(r>>1))&3 swizzle.
// B via cp.async double buffer. Staging reads g_teh/g_ieh (half).
// grid (13 i-blocks, 4 t-blocks, 8 b).
// ============================================================================
#define GT_ZS   0
#define GT_B1   8192
#define GT_W2   11264
#define GT_TE   14336
#define GT_IE   39168
#define GT_A    64000
#define GT_B    96768
#define GT_SMEM 145920
#define TE_STR  776      // padded half stride

__device__ __forceinline__ void gt_fill_b(uint32_t sb, const __half* W1T,
                                          int gs, int tid) {
    const int n0 = (gs >= 24) ? 384 : 0;
    const int k0 = (gs >= 24 ? gs - 24 : gs) * 32;
    const uint32_t base = sb + GT_B + (gs & 1) * 24576;
    #pragma unroll
    for (int it = 0; it < 3; ++it) {
        int idx = tid + it * 512;          // 0..1535 (384 rows x 4 chunks)
        int r = idx >> 2, c = idx & 3;
        uint32_t dst = base + (uint32_t)(r * 64 + (((c + (r >> 1)) & 3) << 4));
        CPA(dst, W1T + (size_t)(n0 + r) * H + k0 + c * 8);
    }
    CPC();
}

__global__ __launch_bounds__(512)
void gate_kernel(const float* __restrict__ b1, const float* __restrict__ W2,
                 const float* __restrict__ b2) {
    extern __shared__ char smem[];
    const uint32_t sb = smem_u32(smem);
    const int tid = threadIdx.x;
    const int wid = tid >> 5, lane = tid & 31;
    const int warp_m = wid >> 3;        // 2 M-groups of 128 rows
    const int warp_n = wid & 7;         // 8 N-groups of 48 cols
    const int b  = blockIdx.z;
    const int t0 = blockIdx.y * 16;
    const int i0 = blockIdx.x * 16;

    float* zs  = (float*)(smem + GT_ZS);        // [8 warp_n][256 rows]
    float* b1s = (float*)(smem + GT_B1);
    float* w2s = (float*)(smem + GT_W2);
    __half* te = (__half*)(smem + GT_TE);
    __half* ie = (__half*)(smem + GT_IE);
    const __half* W1T = g_WTh + 5LL * H * H;

    // issue first B chunk immediately
    gt_fill_b(sb, W1T, 0, tid);

    for (int idx = tid; idx < 2048; idx += 512) zs[idx] = 0.f;
    for (int idx = tid; idx < H; idx += 512) { b1s[idx] = b1[idx]; w2s[idx] = W2[idx]; }

    // stage te/ie (already half in gmem; straight copy into padded stride)
    {
        const __half* teg = g_teh + ((size_t)b * TLEN + t0) * H;
        for (int u = tid; u < 16 * (H / 4); u += 512) {
            int r = u / (H / 4), c4 = (u % (H / 4)) * 4;
            *(uint2*)((char*)te + (r * TE_STR + c4) * 2) =
                *(const uint2*)(teg + r * H + c4);
        }
        const __half* ieg = g_ieh + (size_t)b * ILEN * H;
        for (int u = tid; u < 16 * (H / 4); u += 512) {
            int r = u / (H / 4), c4 = (u % (H / 4)) * 4;
            int gi = i0 + r;
            uint2 v = make_uint2(0u, 0u);
            if (gi < ILEN) v = *(const uint2*)(ieg + (size_t)gi * H + c4);
            *(uint2*)((char*)ie + (r * TE_STR + c4) * 2) = v;
        }
    }
    __syncthreads();

    for (int nc = 0; nc < 2; ++nc) {
        const int n0 = nc * 384;
        uint32_t hacc[96];                 // 8 mi x 6 ni x 2 b32
        #pragma unroll
        for (int q = 0; q < 96; ++q) hacc[q] = 0u;

        for (int kc = 0; kc < 24; ++kc) {
            const int gs = nc * 24 + kc;
            const int buf = gs & 1;
            const int k0 = kc * 32;

            // build A tile: rel = te*ie, 256 rows x 32 halves (64B rows)
            {
                char* ab = smem + GT_A + buf * 16384;
                #pragma unroll
                for (int it = 0; it < 2; ++it) {
                    int idx = tid + it * 512;     // 0..1023 (256 rows x 4 chunks)
                    int r = idx >> 2, c = idx & 3;
                    const __half* tp = te + (r >> 4) * TE_STR + k0 + c * 8;
                    const __half* ip = ie + (r & 15) * TE_STR + k0 + c * 8;
                    uint4 t4 = *(const uint4*)tp;
                    uint4 i4 = *(const uint4*)ip;
                    uint4 p;
                    p.x = hm2(t4.x, i4.x); p.y = hm2(t4.y, i4.y);
                    p.z = hm2(t4.z, i4.z); p.w = hm2(t4.w, i4.w);
                    *(uint4*)(ab + r * 64 + (((c + (r >> 1)) & 3) << 4)) = p;
                }
            }
            CPW0();
            __syncthreads();
            if (gs < 47) gt_fill_b(sb, W1T, gs + 1, tid);

            const uint32_t abase = sb + GT_A + buf * 16384;
            const uint32_t bbase = sb + GT_B + buf * 24576;
            #pragma unroll
            for (int ks = 0; ks < 2; ++ks) {
                uint32_t bf[3][4];
                #pragma unroll
                for (int nip = 0; nip < 3; ++nip) {
                    int g = lane >> 3;
                    int nrow = warp_n * 48 + nip * 16 + ((g >> 1) << 3) + (lane & 7);
                    int cidx = ks * 2 + (g & 1);
                    ldm_x4(bf[nip], bbase +
                        (uint32_t)(nrow * 64 + (((cidx + (nrow >> 1)) & 3) << 4)));
                }
                #pragma unroll
                for (int mi = 0; mi < 8; ++mi) {
                    uint32_t af[4];
                    int rowl = warp_m * 128 + mi * 16 + (lane & 15);
                    int cidx = ks * 2 + (lane >> 4);
                    ldm_x4(af, abase +
                        (uint32_t)(rowl * 64 + (((cidx + (rowl >> 1)) & 3) << 4)));
                    #pragma unroll
                    for (int nip = 0; nip < 3; ++nip) {
                        mma16816h(&hacc[(mi * 6 + nip * 2 + 0) * 2], af, &bf[nip][0]);
                        mma16816h(&hacc[(mi * 6 + nip * 2 + 1) * 2], af, &bf[nip][2]);
                    }
                }
            }
        }

        // N-pass epilogue: unpack fp16 acc, +b1, relu, dot W2 -> zs partials
        #pragma unroll
        for (int mi = 0; mi < 8; ++mi) {
            float z0 = 0.f, z1 = 0.f;
            #pragma unroll
            for (int ni = 0; ni < 6; ++ni) {
                int c = n0 + warp_n * 48 + ni * 8 + (lane & 3) * 2;
                float b1a = b1s[c], b1b = b1s[c + 1];
                float w2a = w2s[c], w2b = w2s[c + 1];
                const uint32_t* hc = &hacc[(mi * 6 + ni) * 2];
                float2 lo = h2f2(hc[0]);
                float2 hi = h2f2(hc[1]);
                z0 += fmaxf(lo.x + b1a, 0.f) * w2a + fmaxf(lo.y + b1b, 0.f) * w2b;
                z1 += fmaxf(hi.x + b1a, 0.f) * w2a + fmaxf(hi.y + b1b, 0.f) * w2b;
            }
            z0 += __shfl_xor_sync(0xffffffffu, z0, 1);
            z0 += __shfl_xor_sync(0xffffffffu, z0, 2);
            z1 += __shfl_xor_sync(0xffffffffu, z1, 1);
            z1 += __shfl_xor_sync(0xffffffffu, z1, 2);
            if ((lane & 3) == 0) {
                int r = warp_m * 128 + mi * 16 + (lane >> 2);
                zs[warp_n * 256 + r]     += z0;
                zs[warp_n * 256 + r + 8] += z1;
            }
        }
    }

    __syncthreads();
    if (tid < 256) {
        float z = b2[0];
        #pragma unroll
        for (int w = 0; w < 8; ++w) z += zs[w * 256 + tid];
        int t_l = tid >> 4, i_l = tid & 15;
        if (i0 + i_l < ILEN)
            g_gate[((size_t)b * TLEN + t0 + t_l) * ILEN + i0 + i_l] = 1.f / (1.f + expf(-z));
    }
}

// ---------------- repack k -> kT[b][h][d][i] ----------------
__global__ __launch_bounds__(256)
void repack_kT_kernel() {
    int idx = blockIdx.x * 256 + threadIdx.x;
    const int total = BSZ*NHEADS*DH*ILEN;
    if (idx >= total) return;
    int i = idx % ILEN;
    int d = (idx / ILEN) % DH;
    int h = (idx / (ILEN*DH)) % NHEADS;
    int b = idx / (ILEN*DH*NHEADS);
    g_kT[idx] = g_k[(b*ILEN + i)*H + h*DH + d];
}

// ---------------- attention: scores -> softmax -> *gate -> ctx ----------------
__global__ __launch_bounds__(256)
void attn_kernel(float* __restrict__ out) {
    __shared__ float q_s[8][DH];
    __shared__ float p_s[8][ILEN + 3];

    const int w    = threadIdx.x >> 5;
    const int lane = threadIdx.x & 31;
    const int b = blockIdx.z, h = blockIdx.y;
    const int t = blockIdx.x * 8 + w;

    const float* qrow = g_q + (b*TLEN + t)*H + h*DH;
    q_s[w][lane]      = qrow[lane];
    q_s[w][lane + 32] = qrow[lane + 32];
    __syncwarp();

    const float* kT = g_kT + (b*NHEADS + h) * DH * ILEN;
    const float scale = 0.125f;

    float mx = -1e30f;
    for (int c = 0; c < 7; ++c) {
        int i = c*32 + lane;
        float s = -1e30f;
        if (i < ILEN) {
            float a0 = 0.f, a1 = 0.f, a2 = 0.f, a3 = 0.f;
            #pragma unroll
            for (int d = 0; d < DH; d += 4) {
                a0 += q_s[w][d+0] * kT[(d+0)*ILEN + i];
                a1 += q_s[w][d+1] * kT[(d+1)*ILEN + i];
                a2 += q_s[w][d+2] * kT[(d+2)*ILEN + i];
                a3 += q_s[w][d+3] * kT[(d+3)*ILEN + i];
            }
            s = (a0 + a1 + a2 + a3) * scale;
            p_s[w][i] = s;
        }
        mx = fmaxf(mx, s);
    }
    #pragma unroll
    for (int off = 16; off; off >>= 1)
        mx = fmaxf(mx, __shfl_xor_sync(0xffffffffu, mx, off));

    float sm = 0.f;
    for (int c = 0; c < 7; ++c) {
        int i = c*32 + lane;
        if (i < ILEN) {
            float e = expf(p_s[w][i] - mx);
            p_s[w][i] = e;
            sm += e;
        }
    }
    #pragma unroll
    for (int off = 16; off; off >>= 1)
        sm += __shfl_xor_sync(0xffffffffu, sm, off);
    float inv = 1.f / sm;

    const float* gaterow = g_gate + (b*TLEN + t)*ILEN;
    for (int c = 0; c < 7; ++c) {
        int i = c*32 + lane;
        if (i < ILEN) p_s[w][i] *= inv * gaterow[i];
    }
    __syncwarp();

    float c0 = 0.f, c1 = 0.f;
    const float* vbase = g_v + b*ILEN*H + h*DH;
    for (int i = 0; i < ILEN; ++i) {
        float p = p_s[w][i];
        c0 += p * vbase[i*H + lane];
        c1 += p * vbase[i*H + lane + 32];
    }
    float* orow = out + (b*TLEN + t)*H + h*DH;
    orow[lane]      = c0;
    orow[lane + 32] = c1;
}

// ---------------- launch ----------------
extern "C" void kernel_launch(void* const* d_in, const int* in_sizes, int n_in,
                              void* d_out, int out_size) {
    const float* text  = (const float*)d_in[0];
    const float* image = (const float*)d_in[1];
    const float* Wq = (const float*)d_in[2];  const float* bq = (const float*)d_in[3];
    const float* Wk = (const float*)d_in[4];  const float* bk = (const float*)d_in[5];
    const float* Wv = (const float*)d_in[6];  const float* bv = (const float*)d_in[7];
    const float* Wt = (const float*)d_in[8];  const float* bt = (const float*)d_in[9];
    const float* Wi = (const float*)d_in[10]; const float* bi = (const float*)d_in[11];
    const float* W1 = (const float*)d_in[12]; const float* b1 = (const float*)d_in[13];
    const float* W2 = (const float*)d_in[14]; const float* b2 = (const float*)d_in[15];
    float* out = (float*)d_out;

    cudaFuncSetAttribute(proj3_kernel, cudaFuncAttributeMaxDynamicSharedMemorySize, PJ_SMEM);
    cudaFuncSetAttribute(proj1_kernel, cudaFuncAttributeMaxDynamicSharedMemorySize, P1_SMEM);
    cudaFuncSetAttribute(gate_kernel,  cudaFuncAttributeMaxDynamicSharedMemorySize, GT_SMEM);

    prep_weights<<<dim3(24, 24, 6), 256>>>(Wt, Wq, Wi, Wk, Wv, W1);
    proj1_kernel<<<dim3(6, 13, 2), 256, P1_SMEM>>>(text, image, bt, bi);
    proj3_kernel<<<dim3(6, 13, 3), 256, PJ_SMEM>>>(text, image, bq, bk, bv);
    repack_kT_kernel<<<(BSZ*NHEADS*DH*ILEN + 255)/256, 256>>>();
    gate_kernel<<<dim3(13, 4, 8), 512, GT_SMEM>>>(b1, W2, b2);
    attn_kernel<<<dim3(TLEN/8, NHEADS, BSZ), 256>>>(out);
}

// round 16
// speedup vs baseline: 1.0674x; 1.0577x over previous
#include <cuda_runtime.h>
#include <cuda_fp16.h>
#include <cstdint>
#include <math.h>

#define H     768
#define BSZ   8
#define TLEN  64
#define ILEN  197
#define NHEADS 12
#define DH    64

// ---------------- device scratch (no allocations allowed) ----------------
__device__ float  g_q   [BSZ*TLEN*H];
__device__ float  g_k   [BSZ*ILEN*H];
__device__ float  g_v   [BSZ*ILEN*H];
__device__ float  g_kT  [BSZ*NHEADS*DH*ILEN];
__device__ float  g_gate[BSZ*TLEN*ILEN];
__device__ __half g_teh [BSZ*TLEN*H];   // text_emb as half (gate input)
__device__ __half g_ieh [BSZ*ILEN*H];   // image_emb as half (gate input)
__device__ __half g_WTh[6*H*H];   // W^T hi halves: Wt,Wq,Wi,Wk,Wv,W1
__device__ __half g_WTl[6*H*H];   // W^T lo residual halves (only 1,3,4 used)

// ---------------- asm helpers (all base-sm_100-legal) ----------------
__device__ __forceinline__ uint32_t smem_u32(const void* p) {
    uint32_t a;
    asm("{ .reg .u64 t; cvta.to.shared.u64 t, %1; cvt.u32.u64 %0, t; }" : "=r"(a) : "l"(p));
    return a;
}
__device__ __forceinline__ void ldm_x4(uint32_t* r, uint32_t addr) {
    asm volatile("ldmatrix.sync.aligned.m8n8.x4.shared.b16 {%0,%1,%2,%3}, [%4];"
        : "=r"(r[0]), "=r"(r[1]), "=r"(r[2]), "=r"(r[3]) : "r"(addr));
}
__device__ __forceinline__ void ldm_x2(uint32_t* r, uint32_t addr) {
    asm volatile("ldmatrix.sync.aligned.m8n8.x2.shared.b16 {%0,%1}, [%2];"
        : "=r"(r[0]), "=r"(r[1]) : "r"(addr));
}
// fp32-accumulator mma (projections)
__device__ __forceinline__ void mma16816(float* c, const uint32_t* a, const uint32_t* b) {
    asm volatile("mma.sync.aligned.m16n8k16.row.col.f32.f16.f16.f32 "
        "{%0,%1,%2,%3}, {%4,%5,%6,%7}, {%8,%9}, {%0,%1,%2,%3};"
        : "+f"(c[0]), "+f"(c[1]), "+f"(c[2]), "+f"(c[3])
        : "r"(a[0]), "r"(a[1]), "r"(a[2]), "r"(a[3]), "r"(b[0]), "r"(b[1]));
}
// fp16-accumulator mma (gate MLP)
__device__ __forceinline__ void mma16816h(uint32_t* c, const uint32_t* a, const uint32_t* b) {
    asm volatile("mma.sync.aligned.m16n8k16.row.col.f16.f16.f16.f16 "
        "{%0,%1}, {%2,%3,%4,%5}, {%6,%7}, {%0,%1};"
        : "+r"(c[0]), "+r"(c[1])
        : "r"(a[0]), "r"(a[1]), "r"(a[2]), "r"(a[3]), "r"(b[0]), "r"(b[1]));
}
__device__ __forceinline__ uint32_t hm2(uint32_t a, uint32_t b) {
    uint32_t r; asm("mul.f16x2 %0, %1, %2;" : "=r"(r) : "r"(a), "r"(b)); return r;
}
__device__ __forceinline__ uint32_t h2bits(__half2 h) { return *reinterpret_cast<uint32_t*>(&h); }
__device__ __forceinline__ float2 h2f2(uint32_t u) {
    return __half22float2(*reinterpret_cast<__half2*>(&u));
}
#define CPA(dst, src) asm volatile("cp.async.cg.shared.global [%0], [%1], 16;" :: "r"(dst), "l"(src))
#define CPC() asm volatile("cp.async.commit_group;" ::: "memory")
#define CPW0() asm volatile("cp.async.wait_group 0;" ::: "memory")

// ---------------- prep: transpose weights, split into hi/lo halves ----------------
__global__ __launch_bounds__(256)
void prep_weights(const float* __restrict__ Wt, const float* __restrict__ Wq,
                  const float* __restrict__ Wi, const float* __restrict__ Wk,
                  const float* __restrict__ Wv, const float* __restrict__ W1) {
    __shared__ float ts[32][33];
    const int zz = blockIdx.z;
    const float* in = (zz == 0) ? Wt : (zz == 1) ? Wq :
                      (zz == 2) ? Wi : (zz == 3) ? Wk :
                      (zz == 4) ? Wv : W1;
    const bool need_lo = (zz == 1) || (zz == 3) || (zz == 4);
    __half* oh = g_WTh + (size_t)zz * H * H;
    __half* ol = g_WTl + (size_t)zz * H * H;
    int x0 = blockIdx.x * 32, y0 = blockIdx.y * 32;
    int tx = threadIdx.x & 31, ty = threadIdx.x >> 5;
    #pragma unroll
    for (int j = 0; j < 32; j += 8)
        ts[ty + j][tx] = in[(y0 + ty + j) * H + x0 + tx];
    __syncthreads();
    #pragma unroll
    for (int j = 0; j < 32; j += 8) {
        float v = ts[tx][ty + j];
        __half h = __float2half_rn(v);
        int o = (x0 + ty + j) * H + y0 + tx;
        oh[o] = h;
        if (need_lo) ol[o] = __float2half_rn(v - __half2float(h));
    }
}

// ============================================================================
// proj_all: one launch for all 5 projections.
// z=0: te (1-MMA -> g_teh half)   z=1: ie (1-MMA -> g_ieh half)
// z=2: q  (3-MMA split, fp32)     z=3: k (3-MMA)      z=4: v (3-MMA)
// M-tile 128, N-tile 128, K chunks of 64, 256 thr (8 warps 2Mx4N).
// ============================================================================
#define PJ_AH 0
#define PJ_AL 32768
#define PJ_BH 65536
#define PJ_BL 98304
#define PJ_SMEM 131072

__device__ __forceinline__ void pj_fill_b(uint32_t sb, size_t wofs, bool split,
                                          int n0, int k0, int buf, int tid) {
    int row = tid >> 1;
    int c0  = (tid & 1) * 4;
    size_t src = wofs + (size_t)(n0 + row) * H + k0;
    uint32_t dh = sb + PJ_BH + buf * 16384 + row * 128;
    uint32_t dl = sb + PJ_BL + buf * 16384 + row * 128;
    #pragma unroll
    for (int q = 0; q < 4; ++q) {
        int cidx = c0 + q;
        uint32_t sw = (uint32_t)((cidx ^ (row & 7)) << 4);
        CPA(dh + sw, g_WTh + src + cidx * 8);
        if (split) CPA(dl + sw, g_WTl + src + cidx * 8);
    }
    CPC();
}

__global__ __launch_bounds__(256)
void proj_all_kernel(const float* __restrict__ text, const float* __restrict__ image,
                     const float* __restrict__ bt, const float* __restrict__ bi,
                     const float* __restrict__ bq, const float* __restrict__ bk,
                     const float* __restrict__ bv) {
    const int z = blockIdx.z;                 // 0=te,1=ie,2=q,3=k,4=v
    const bool split  = (z >= 2);
    const bool istext = (z == 0 || z == 2);
    const int M = istext ? BSZ * TLEN : BSZ * ILEN;
    const int m0 = blockIdx.y * 128;
    if (m0 >= M) return;
    const int n0 = blockIdx.x * 128;

    const float* A = istext ? text : image;
    const int widx = (z == 0) ? 0 : (z == 1) ? 2 : (z == 2) ? 1 : z;  // Wt,Wi,Wq,Wk,Wv
    const size_t wofs = (size_t)widx * H * H;
    const float* bias = (z == 0) ? bt : (z == 1) ? bi :
                        (z == 2) ? bq : (z == 3) ? bk : bv;

    extern __shared__ char smem[];
    const uint32_t sb = smem_u32(smem);
    const int tid = threadIdx.x;
    const int wid = tid >> 5, lane = tid & 31;
    const int warp_m = wid & 1, warp_n = wid >> 1;

    float acc[64];
    #pragma unroll
    for (int q = 0; q < 64; ++q) acc[q] = 0.f;

    pj_fill_b(sb, wofs, split, n0, 0, 0, tid);

    for (int kc = 0; kc < 12; ++kc) {
        const int buf = kc & 1;
        const int k0 = kc * 64;
        {
            int row = tid >> 1, hs = tid & 1;
            int grow = m0 + row;
            bool valid = grow < M;
            const float* src = A + (size_t)grow * H + k0 + hs * 32;
            char* ah = smem + PJ_AH + buf * 16384 + row * 128;
            char* al = smem + PJ_AL + buf * 16384 + row * 128;
            #pragma unroll
            for (int q = 0; q < 4; ++q) {
                int cidx = hs * 4 + q;
                float4 v0 = valid ? *(const float4*)(src + q * 8)
                                  : make_float4(0.f, 0.f, 0.f, 0.f);
                float4 v1 = valid ? *(const float4*)(src + q * 8 + 4)
                                  : make_float4(0.f, 0.f, 0.f, 0.f);
                float e[8] = {v0.x, v0.y, v0.z, v0.w, v1.x, v1.y, v1.z, v1.w};
                uint4 hv;
                uint32_t* hp = &hv.x;
                __half hs2[8];
                #pragma unroll
                for (int j = 0; j < 4; ++j) {
                    hs2[2*j]   = __float2half_rn(e[2*j]);
                    hs2[2*j+1] = __float2half_rn(e[2*j+1]);
                    hp[j] = h2bits(__halves2half2(hs2[2*j], hs2[2*j+1]));
                }
                uint32_t sw = (uint32_t)((cidx ^ (row & 7)) << 4);
                *(uint4*)(ah + sw) = hv;
                if (split) {
                    uint4 lv;
                    uint32_t* lp = &lv.x;
                    #pragma unroll
                    for (int j = 0; j < 4; ++j) {
                        __half la = __float2half_rn(e[2*j]   - __half2float(hs2[2*j]));
                        __half lb = __float2half_rn(e[2*j+1] - __half2float(hs2[2*j+1]));
                        lp[j] = h2bits(__halves2half2(la, lb));
                    }
                    *(uint4*)(al + sw) = lv;
                }
            }
        }
        CPW0();
        __syncthreads();
        if (kc < 11) pj_fill_b(sb, wofs, split, n0, (kc + 1) * 64, buf ^ 1, tid);

        const uint32_t ahb = sb + PJ_AH + buf * 16384;
        const uint32_t alb = sb + PJ_AL + buf * 16384;
        const uint32_t bhb = sb + PJ_BH + buf * 16384;
        const uint32_t blb = sb + PJ_BL + buf * 16384;
        #pragma unroll
        for (int ks = 0; ks < 4; ++ks) {
            uint32_t afh[4][4];
            #pragma unroll
            for (int mi = 0; mi < 4; ++mi) {
                int rowl = warp_m * 64 + mi * 16 + (lane & 15);
                int cidx = ks * 2 + (lane >> 4);
                ldm_x4(afh[mi], ahb + (uint32_t)(rowl * 128 + ((cidx ^ (rowl & 7)) << 4)));
            }
            uint32_t bfh[4][2];
            #pragma unroll
            for (int ni = 0; ni < 4; ++ni) {
                int nrow = warp_n * 32 + ni * 8 + (lane & 7);
                int cidx = ks * 2 + ((lane >> 3) & 1);
                ldm_x2(bfh[ni], bhb + (uint32_t)(nrow * 128 + ((cidx ^ (nrow & 7)) << 4)));
            }
            #pragma unroll
            for (int mi = 0; mi < 4; ++mi)
                #pragma unroll
                for (int ni = 0; ni < 4; ++ni)
                    mma16816(&acc[(mi * 4 + ni) * 4], afh[mi], bfh[ni]);
            if (split) {
                uint32_t afl[4][4];
                #pragma unroll
                for (int mi = 0; mi < 4; ++mi) {
                    int rowl = warp_m * 64 + mi * 16 + (lane & 15);
                    int cidx = ks * 2 + (lane >> 4);
                    ldm_x4(afl[mi], alb + (uint32_t)(rowl * 128 + ((cidx ^ (rowl & 7)) << 4)));
                }
                uint32_t bfl[4][2];
                #pragma unroll
                for (int ni = 0; ni < 4; ++ni) {
                    int nrow = warp_n * 32 + ni * 8 + (lane & 7);
                    int cidx = ks * 2 + ((lane >> 3) & 1);
                    ldm_x2(bfl[ni], blb + (uint32_t)(nrow * 128 + ((cidx ^ (nrow & 7)) << 4)));
                }
                #pragma unroll
                for (int mi = 0; mi < 4; ++mi)
                    #pragma unroll
                    for (int ni = 0; ni < 4; ++ni) {
                        float* cc = &acc[(mi * 4 + ni) * 4];
                        mma16816(cc, afl[mi], bfh[ni]);
                        mma16816(cc, afh[mi], bfl[ni]);
                    }
            }
        }
    }

    // epilogue
    #pragma unroll
    for (int mi = 0; mi < 4; ++mi) {
        #pragma unroll
        for (int ni = 0; ni < 4; ++ni) {
            int r = m0 + warp_m * 64 + mi * 16 + (lane >> 2);
            int c = n0 + warp_n * 32 + ni * 8 + (lane & 3) * 2;
            float ba = __ldg(&bias[c]), bb = __ldg(&bias[c + 1]);
            const float* cc = &acc[(mi * 4 + ni) * 4];
            if (z <= 1) {
                __half* C = (z == 0) ? g_teh : g_ieh;
                if (r < M)
                    *(__half2*)(C + (size_t)r * H + c) = __floats2half2_rn(cc[0] + ba, cc[1] + bb);
                if (r + 8 < M)
                    *(__half2*)(C + (size_t)(r + 8) * H + c) = __floats2half2_rn(cc[2] + ba, cc[3] + bb);
            } else {
                float* C = (z == 2) ? g_q : (z == 3) ? g_k : g_v;
                if (r < M)     *(float2*)(C + (size_t)r * H + c)       = make_float2(cc[0] + ba, cc[1] + bb);
                if (r + 8 < M) *(float2*)(C + (size_t)(r + 8) * H + c) = make_float2(cc[2] + ba, cc[3] + bb);
            }
        }
    }
}

// ============================================================================
// Gate kernel (R10 config — best measured 398.6us): M=256 (16t x 16i),
// N=384 per pass (2 passes), K-chunk 32. 512 thr, 16 warps 2M x 8N,
// warp tile 128x48, fp16 acc. 64B-row SMEM tiles, (c+(r>>1))&3 swizzle.
// B via cp.async double buffer. Staging reads g_teh/g_ieh (half).
// grid (13 i-blocks, 4 t-blocks, 8 b).
// ============================================================================
#define GT_ZS   0
#define GT_B1   8192
#define GT_W2   11264
#define GT_TE   14336
#define GT_IE   39168
#define GT_A    64000
#define GT_B    96768
#define GT_SMEM 145920
#define TE_STR  776      // padded half stride

__device__ __forceinline__ void gt_fill_b(uint32_t sb, const __half* W1T,
                                          int gs, int tid) {
    const int n0 = (gs >= 24) ? 384 : 0;
    const int k0 = (gs >= 24 ? gs - 24 : gs) * 32;
    const uint32_t base = sb + GT_B + (gs & 1) * 24576;
    #pragma unroll
    for (int it = 0; it < 3; ++it) {
        int idx = tid + it * 512;          // 0..1535 (384 rows x 4 chunks)
        int r = idx >> 2, c = idx & 3;
        uint32_t dst = base + (uint32_t)(r * 64 + (((c + (r >> 1)) & 3) << 4));
        CPA(dst, W1T + (size_t)(n0 + r) * H + k0 + c * 8);
    }
    CPC();
}

__global__ __launch_bounds__(512)
void gate_kernel(const float* __restrict__ b1, const float* __restrict__ W2,
                 const float* __restrict__ b2) {
    extern __shared__ char smem[];
    const uint32_t sb = smem_u32(smem);
    const int tid = threadIdx.x;
    const int wid = tid >> 5, lane = tid & 31;
    const int warp_m = wid >> 3;        // 2 M-groups of 128 rows
    const int warp_n = wid & 7;         // 8 N-groups of 48 cols
    const int b  = blockIdx.z;
    const int t0 = blockIdx.y * 16;
    const int i0 = blockIdx.x * 16;

    float* zs  = (float*)(smem + GT_ZS);        // [8 warp_n][256 rows]
    float* b1s = (float*)(smem + GT_B1);
    float* w2s = (float*)(smem + GT_W2);
    __half* te = (__half*)(smem + GT_TE);
    __half* ie = (__half*)(smem + GT_IE);
    const __half* W1T = g_WTh + 5LL * H * H;

    // issue first B chunk immediately
    gt_fill_b(sb, W1T, 0, tid);

    for (int idx = tid; idx < 2048; idx += 512) zs[idx] = 0.f;
    for (int idx = tid; idx < H; idx += 512) { b1s[idx] = b1[idx]; w2s[idx] = W2[idx]; }

    // stage te/ie (already half in gmem; straight copy into padded stride)
    {
        const __half* teg = g_teh + ((size_t)b * TLEN + t0) * H;
        for (int u = tid; u < 16 * (H / 4); u += 512) {
            int r = u / (H / 4), c4 = (u % (H / 4)) * 4;
            *(uint2*)((char*)te + (r * TE_STR + c4) * 2) =
                *(const uint2*)(teg + r * H + c4);
        }
        const __half* ieg = g_ieh + (size_t)b * ILEN * H;
        for (int u = tid; u < 16 * (H / 4); u += 512) {
            int r = u / (H / 4), c4 = (u % (H / 4)) * 4;
            int gi = i0 + r;
            uint2 v = make_uint2(0u, 0u);
            if (gi < ILEN) v = *(const uint2*)(ieg + (size_t)gi * H + c4);
            *(uint2*)((char*)ie + (r * TE_STR + c4) * 2) = v;
        }
    }
    __syncthreads();

    for (int nc = 0; nc < 2; ++nc) {
        const int n0 = nc * 384;
        uint32_t hacc[96];                 // 8 mi x 6 ni x 2 b32
        #pragma unroll
        for (int q = 0; q < 96; ++q) hacc[q] = 0u;

        for (int kc = 0; kc < 24; ++kc) {
            const int gs = nc * 24 + kc;
            const int buf = gs & 1;
            const int k0 = kc * 32;

            // build A tile: rel = te*ie, 256 rows x 32 halves (64B rows)
            {
                char* ab = smem + GT_A + buf * 16384;
                #pragma unroll
                for (int it = 0; it < 2; ++it) {
                    int idx = tid + it * 512;     // 0..1023 (256 rows x 4 chunks)
                    int r = idx >> 2, c = idx & 3;
                    const __half* tp = te + (r >> 4) * TE_STR + k0 + c * 8;
                    const __half* ip = ie + (r & 15) * TE_STR + k0 + c * 8;
                    uint4 t4 = *(const uint4*)tp;
                    uint4 i4 = *(const uint4*)ip;
                    uint4 p;
                    p.x = hm2(t4.x, i4.x); p.y = hm2(t4.y, i4.y);
                    p.z = hm2(t4.z, i4.z); p.w = hm2(t4.w, i4.w);
                    *(uint4*)(ab + r * 64 + (((c + (r >> 1)) & 3) << 4)) = p;
                }
            }
            CPW0();
            __syncthreads();
            if (gs < 47) gt_fill_b(sb, W1T, gs + 1, tid);

            const uint32_t abase = sb + GT_A + buf * 16384;
            const uint32_t bbase = sb + GT_B + buf * 24576;
            #pragma unroll
            for (int ks = 0; ks < 2; ++ks) {
                uint32_t bf[3][4];
                #pragma unroll
                for (int nip = 0; nip < 3; ++nip) {
                    int g = lane >> 3;
                    int nrow = warp_n * 48 + nip * 16 + ((g >> 1) << 3) + (lane & 7);
                    int cidx = ks * 2 + (g & 1);
                    ldm_x4(bf[nip], bbase +
                        (uint32_t)(nrow * 64 + (((cidx + (nrow >> 1)) & 3) << 4)));
                }
                #pragma unroll
                for (int mi = 0; mi < 8; ++mi) {
                    uint32_t af[4];
                    int rowl = warp_m * 128 + mi * 16 + (lane & 15);
                    int cidx = ks * 2 + (lane >> 4);
                    ldm_x4(af, abase +
                        (uint32_t)(rowl * 64 + (((cidx + (rowl >> 1)) & 3) << 4)));
                    #pragma unroll
                    for (int nip = 0; nip < 3; ++nip) {
                        mma16816h(&hacc[(mi * 6 + nip * 2 + 0) * 2], af, &bf[nip][0]);
                        mma16816h(&hacc[(mi * 6 + nip * 2 + 1) * 2], af, &bf[nip][2]);
                    }
                }
            }
        }

        // N-pass epilogue: unpack fp16 acc, +b1, relu, dot W2 -> zs partials
        #pragma unroll
        for (int mi = 0; mi < 8; ++mi) {
            float z0 = 0.f, z1 = 0.f;
            #pragma unroll
            for (int ni = 0; ni < 6; ++ni) {
                int c = n0 + warp_n * 48 + ni * 8 + (lane & 3) * 2;
                float b1a = b1s[c], b1b = b1s[c + 1];
                float w2a = w2s[c], w2b = w2s[c + 1];
                const uint32_t* hc = &hacc[(mi * 6 + ni) * 2];
                float2 lo = h2f2(hc[0]);
                float2 hi = h2f2(hc[1]);
                z0 += fmaxf(lo.x + b1a, 0.f) * w2a + fmaxf(lo.y + b1b, 0.f) * w2b;
                z1 += fmaxf(hi.x + b1a, 0.f) * w2a + fmaxf(hi.y + b1b, 0.f) * w2b;
            }
            z0 += __shfl_xor_sync(0xffffffffu, z0, 1);
            z0 += __shfl_xor_sync(0xffffffffu, z0, 2);
            z1 += __shfl_xor_sync(0xffffffffu, z1, 1);
            z1 += __shfl_xor_sync(0xffffffffu, z1, 2);
            if ((lane & 3) == 0) {
                int r = warp_m * 128 + mi * 16 + (lane >> 2);
                zs[warp_n * 256 + r]     += z0;
                zs[warp_n * 256 + r + 8] += z1;
            }
        }
    }

    __syncthreads();
    if (tid < 256) {
        float z = b2[0];
        #pragma unroll
        for (int w = 0; w < 8; ++w) z += zs[w * 256 + tid];
        int t_l = tid >> 4, i_l = tid & 15;
        if (i0 + i_l < ILEN)
            g_gate[((size_t)b * TLEN + t0 + t_l) * ILEN + i0 + i_l] = 1.f / (1.f + expf(-z));
    }
}

// ---------------- repack k -> kT[b][h][d][i] ----------------
__global__ __launch_bounds__(256)
void repack_kT_kernel() {
    int idx = blockIdx.x * 256 + threadIdx.x;
    const int total = BSZ*NHEADS*DH*ILEN;
    if (idx >= total) return;
    int i = idx % ILEN;
    int d = (idx / ILEN) % DH;
    int h = (idx / (ILEN*DH)) % NHEADS;
    int b = idx / (ILEN*DH*NHEADS);
    g_kT[idx] = g_k[(b*ILEN + i)*H + h*DH + d];
}

// ---------------- attention: scores -> softmax -> *gate -> ctx ----------------
__global__ __launch_bounds__(256)
void attn_kernel(float* __restrict__ out) {
    __shared__ float q_s[8][DH];
    __shared__ float p_s[8][ILEN + 3];

    const int w    = threadIdx.x >> 5;
    const int lane = threadIdx.x & 31;
    const int b = blockIdx.z, h = blockIdx.y;
    const int t = blockIdx.x * 8 + w;

    const float* qrow = g_q + (b*TLEN + t)*H + h*DH;
    q_s[w][lane]      = qrow[lane];
    q_s[w][lane + 32] = qrow[lane + 32];
    __syncwarp();

    const float* kT = g_kT + (b*NHEADS + h) * DH * ILEN;
    const float scale = 0.125f;

    float mx = -1e30f;
    for (int c = 0; c < 7; ++c) {
        int i = c*32 + lane;
        float s = -1e30f;
        if (i < ILEN) {
            float a0 = 0.f, a1 = 0.f, a2 = 0.f, a3 = 0.f;
            #pragma unroll
            for (int d = 0; d < DH; d += 4) {
                a0 += q_s[w][d+0] * kT[(d+0)*ILEN + i];
                a1 += q_s[w][d+1] * kT[(d+1)*ILEN + i];
                a2 += q_s[w][d+2] * kT[(d+2)*ILEN + i];
                a3 += q_s[w][d+3] * kT[(d+3)*ILEN + i];
            }
            s = (a0 + a1 + a2 + a3) * scale;
            p_s[w][i] = s;
        }
        mx = fmaxf(mx, s);
    }
    #pragma unroll
    for (int off = 16; off; off >>= 1)
        mx = fmaxf(mx, __shfl_xor_sync(0xffffffffu, mx, off));

    float sm = 0.f;
    for (int c = 0; c < 7; ++c) {
        int i = c*32 + lane;
        if (i < ILEN) {
            float e = expf(p_s[w][i] - mx);
            p_s[w][i] = e;
            sm += e;
        }
    }
    #pragma unroll
    for (int off = 16; off; off >>= 1)
        sm += __shfl_xor_sync(0xffffffffu, sm, off);
    float inv = 1.f / sm;

    const float* gaterow = g_gate + (b*TLEN + t)*ILEN;
    for (int c = 0; c < 7; ++c) {
        int i = c*32 + lane;
        if (i < ILEN) p_s[w][i] *= inv * gaterow[i];
    }
    __syncwarp();

    float c0 = 0.f, c1 = 0.f;
    const float* vbase = g_v + b*ILEN*H + h*DH;
    for (int i = 0; i < ILEN; ++i) {
        float p = p_s[w][i];
        c0 += p * vbase[i*H + lane];
        c1 += p * vbase[i*H + lane + 32];
    }
    float* orow = out + (b*TLEN + t)*H + h*DH;
    orow[lane]      = c0;
    orow[lane + 32] = c1;
}

// ---------------- launch ----------------
extern "C" void kernel_launch(void* const* d_in, const int* in_sizes, int n_in,
                              void* d_out, int out_size) {
    const float* text  = (const float*)d_in[0];
    const float* image = (const float*)d_in[1];
    const float* Wq = (const float*)d_in[2];  const float* bq = (const float*)d_in[3];
    const float* Wk = (const float*)d_in[4];  const float* bk = (const float*)d_in[5];
    const float* Wv = (const float*)d_in[6];  const float* bv = (const float*)d_in[7];
    const float* Wt = (const float*)d_in[8];  const float* bt = (const float*)d_in[9];
    const float* Wi = (const float*)d_in[10]; const float* bi = (const float*)d_in[11];
    const float* W1 = (const float*)d_in[12]; const float* b1 = (const float*)d_in[13];
    const float* W2 = (const float*)d_in[14]; const float* b2 = (const float*)d_in[15];
    float* out = (float*)d_out;

    cudaFuncSetAttribute(proj_all_kernel, cudaFuncAttributeMaxDynamicSharedMemorySize, PJ_SMEM);
    cudaFuncSetAttribute(gate_kernel,     cudaFuncAttributeMaxDynamicSharedMemorySize, GT_SMEM);

    prep_weights<<<dim3(24, 24, 6), 256>>>(Wt, Wq, Wi, Wk, Wv, W1);
    proj_all_kernel<<<dim3(6, 13, 5), 256, PJ_SMEM>>>(text, image, bt, bi, bq, bk, bv);
    repack_kT_kernel<<<(BSZ*NHEADS*DH*ILEN + 255)/256, 256>>>();
    gate_kernel<<<dim3(13, 4, 8), 512, GT_SMEM>>>(b1, W2, b2);
    attn_kernel<<<dim3(TLEN/8, NHEADS, BSZ), 256>>>(out);
}

// round 17
// speedup vs baseline: 1.1164x; 1.0459x over previous
#include <cuda_runtime.h>
#include <cuda_fp16.h>
#include <cstdint>
#include <math.h>

#define H     768
#define BSZ   8
#define TLEN  64
#define ILEN  197
#define NHEADS 12
#define DH    64

// ---------------- device scratch (no allocations allowed) ----------------
__device__ float  g_q   [BSZ*TLEN*H];
__device__ float  g_k   [BSZ*ILEN*H];
__device__ float  g_v   [BSZ*ILEN*H];
__device__ float  g_kT  [BSZ*NHEADS*DH*ILEN];
__device__ float  g_gate[BSZ*TLEN*ILEN];
__device__ __half g_teh [BSZ*TLEN*H];   // text_emb as half (gate input)
__device__ __half g_ieh [BSZ*ILEN*H];   // image_emb as half (gate input)
__device__ __half g_WTh[6*H*H];   // W^T hi halves: Wt,Wq,Wi,Wk,Wv,W1
__device__ __half g_WTl[6*H*H];   // W^T lo residual halves (only 1,3,4 used)

// ---------------- asm helpers (all base-sm_100-legal) ----------------
__device__ __forceinline__ uint32_t smem_u32(const void* p) {
    uint32_t a;
    asm("{ .reg .u64 t; cvta.to.shared.u64 t, %1; cvt.u32.u64 %0, t; }" : "=r"(a) : "l"(p));
    return a;
}
__device__ __forceinline__ void ldm_x4(uint32_t* r, uint32_t addr) {
    asm volatile("ldmatrix.sync.aligned.m8n8.x4.shared.b16 {%0,%1,%2,%3}, [%4];"
        : "=r"(r[0]), "=r"(r[1]), "=r"(r[2]), "=r"(r[3]) : "r"(addr));
}
__device__ __forceinline__ void ldm_x2(uint32_t* r, uint32_t addr) {
    asm volatile("ldmatrix.sync.aligned.m8n8.x2.shared.b16 {%0,%1}, [%2];"
        : "=r"(r[0]), "=r"(r[1]) : "r"(addr));
}
// fp32-accumulator mma (projections)
__device__ __forceinline__ void mma16816(float* c, const uint32_t* a, const uint32_t* b) {
    asm volatile("mma.sync.aligned.m16n8k16.row.col.f32.f16.f16.f32 "
        "{%0,%1,%2,%3}, {%4,%5,%6,%7}, {%8,%9}, {%0,%1,%2,%3};"
        : "+f"(c[0]), "+f"(c[1]), "+f"(c[2]), "+f"(c[3])
        : "r"(a[0]), "r"(a[1]), "r"(a[2]), "r"(a[3]), "r"(b[0]), "r"(b[1]));
}
// fp16-accumulator mma (gate MLP)
__device__ __forceinline__ void mma16816h(uint32_t* c, const uint32_t* a, const uint32_t* b) {
    asm volatile("mma.sync.aligned.m16n8k16.row.col.f16.f16.f16.f16 "
        "{%0,%1}, {%2,%3,%4,%5}, {%6,%7}, {%0,%1};"
        : "+r"(c[0]), "+r"(c[1])
        : "r"(a[0]), "r"(a[1]), "r"(a[2]), "r"(a[3]), "r"(b[0]), "r"(b[1]));
}
__device__ __forceinline__ uint32_t hm2(uint32_t a, uint32_t b) {
    uint32_t r; asm("mul.f16x2 %0, %1, %2;" : "=r"(r) : "r"(a), "r"(b)); return r;
}
__device__ __forceinline__ uint32_t h2bits(__half2 h) { return *reinterpret_cast<uint32_t*>(&h); }
__device__ __forceinline__ float2 h2f2(uint32_t u) {
    return __half22float2(*reinterpret_cast<__half2*>(&u));
}
#define CPA(dst, src) asm volatile("cp.async.cg.shared.global [%0], [%1], 16;" :: "r"(dst), "l"(src))
#define CPC() asm volatile("cp.async.commit_group;" ::: "memory")
#define CPW0() asm volatile("cp.async.wait_group 0;" ::: "memory")

// ---------------- prep: transpose weights, split into hi/lo halves ----------------
__global__ __launch_bounds__(256)
void prep_weights(const float* __restrict__ Wt, const float* __restrict__ Wq,
                  const float* __restrict__ Wi, const float* __restrict__ Wk,
                  const float* __restrict__ Wv, const float* __restrict__ W1) {
    __shared__ float ts[32][33];
    const int zz = blockIdx.z;
    const float* in = (zz == 0) ? Wt : (zz == 1) ? Wq :
                      (zz == 2) ? Wi : (zz == 3) ? Wk :
                      (zz == 4) ? Wv : W1;
    const bool need_lo = (zz == 1) || (zz == 3) || (zz == 4);
    __half* oh = g_WTh + (size_t)zz * H * H;
    __half* ol = g_WTl + (size_t)zz * H * H;
    int x0 = blockIdx.x * 32, y0 = blockIdx.y * 32;
    int tx = threadIdx.x & 31, ty = threadIdx.x >> 5;
    #pragma unroll
    for (int j = 0; j < 32; j += 8)
        ts[ty + j][tx] = in[(y0 + ty + j) * H + x0 + tx];
    __syncthreads();
    #pragma unroll
    for (int j = 0; j < 32; j += 8) {
        float v = ts[tx][ty + j];
        __half h = __float2half_rn(v);
        int o = (x0 + ty + j) * H + y0 + tx;
        oh[o] = h;
        if (need_lo) ol[o] = __float2half_rn(v - __half2float(h));
    }
}

// ============================================================================
// proj_all (zbase param): z=0 te, 1 ie (1-MMA half out); z=2 q, 3 k, 4 v
// (3-MMA split, fp32 out). M-tile 128, N-tile 128, K chunks of 64, 256 thr.
// ============================================================================
#define PJ_AH 0
#define PJ_AL 32768
#define PJ_BH 65536
#define PJ_BL 98304
#define PJ_SMEM 131072

__device__ __forceinline__ void pj_fill_b(uint32_t sb, size_t wofs, bool split,
                                          int n0, int k0, int buf, int tid) {
    int row = tid >> 1;
    int c0  = (tid & 1) * 4;
    size_t src = wofs + (size_t)(n0 + row) * H + k0;
    uint32_t dh = sb + PJ_BH + buf * 16384 + row * 128;
    uint32_t dl = sb + PJ_BL + buf * 16384 + row * 128;
    #pragma unroll
    for (int q = 0; q < 4; ++q) {
        int cidx = c0 + q;
        uint32_t sw = (uint32_t)((cidx ^ (row & 7)) << 4);
        CPA(dh + sw, g_WTh + src + cidx * 8);
        if (split) CPA(dl + sw, g_WTl + src + cidx * 8);
    }
    CPC();
}

__global__ __launch_bounds__(256)
void proj_all_kernel(const float* __restrict__ text, const float* __restrict__ image,
                     const float* __restrict__ bt, const float* __restrict__ bi,
                     const float* __restrict__ bq, const float* __restrict__ bk,
                     const float* __restrict__ bv, int zbase) {
    const int z = blockIdx.z + zbase;         // 0=te,1=ie,2=q,3=k,4=v
    const bool split  = (z >= 2);
    const bool istext = (z == 0 || z == 2);
    const int M = istext ? BSZ * TLEN : BSZ * ILEN;
    const int m0 = blockIdx.y * 128;
    if (m0 >= M) return;
    const int n0 = blockIdx.x * 128;

    const float* A = istext ? text : image;
    const int widx = (z == 0) ? 0 : (z == 1) ? 2 : (z == 2) ? 1 : z;  // Wt,Wi,Wq,Wk,Wv
    const size_t wofs = (size_t)widx * H * H;
    const float* bias = (z == 0) ? bt : (z == 1) ? bi :
                        (z == 2) ? bq : (z == 3) ? bk : bv;

    extern __shared__ char smem[];
    const uint32_t sb = smem_u32(smem);
    const int tid = threadIdx.x;
    const int wid = tid >> 5, lane = tid & 31;
    const int warp_m = wid & 1, warp_n = wid >> 1;

    float acc[64];
    #pragma unroll
    for (int q = 0; q < 64; ++q) acc[q] = 0.f;

    pj_fill_b(sb, wofs, split, n0, 0, 0, tid);

    for (int kc = 0; kc < 12; ++kc) {
        const int buf = kc & 1;
        const int k0 = kc * 64;
        {
            int row = tid >> 1, hs = tid & 1;
            int grow = m0 + row;
            bool valid = grow < M;
            const float* src = A + (size_t)grow * H + k0 + hs * 32;
            char* ah = smem + PJ_AH + buf * 16384 + row * 128;
            char* al = smem + PJ_AL + buf * 16384 + row * 128;
            #pragma unroll
            for (int q = 0; q < 4; ++q) {
                int cidx = hs * 4 + q;
                float4 v0 = valid ? *(const float4*)(src + q * 8)
                                  : make_float4(0.f, 0.f, 0.f, 0.f);
                float4 v1 = valid ? *(const float4*)(src + q * 8 + 4)
                                  : make_float4(0.f, 0.f, 0.f, 0.f);
                float e[8] = {v0.x, v0.y, v0.z, v0.w, v1.x, v1.y, v1.z, v1.w};
                uint4 hv;
                uint32_t* hp = &hv.x;
                __half hs2[8];
                #pragma unroll
                for (int j = 0; j < 4; ++j) {
                    hs2[2*j]   = __float2half_rn(e[2*j]);
                    hs2[2*j+1] = __float2half_rn(e[2*j+1]);
                    hp[j] = h2bits(__halves2half2(hs2[2*j], hs2[2*j+1]));
                }
                uint32_t sw = (uint32_t)((cidx ^ (row & 7)) << 4);
                *(uint4*)(ah + sw) = hv;
                if (split) {
                    uint4 lv;
                    uint32_t* lp = &lv.x;
                    #pragma unroll
                    for (int j = 0; j < 4; ++j) {
                        __half la = __float2half_rn(e[2*j]   - __half2float(hs2[2*j]));
                        __half lb = __float2half_rn(e[2*j+1] - __half2float(hs2[2*j+1]));
                        lp[j] = h2bits(__halves2half2(la, lb));
                    }
                    *(uint4*)(al + sw) = lv;
                }
            }
        }
        CPW0();
        __syncthreads();
        if (kc < 11) pj_fill_b(sb, wofs, split, n0, (kc + 1) * 64, buf ^ 1, tid);

        const uint32_t ahb = sb + PJ_AH + buf * 16384;
        const uint32_t alb = sb + PJ_AL + buf * 16384;
        const uint32_t bhb = sb + PJ_BH + buf * 16384;
        const uint32_t blb = sb + PJ_BL + buf * 16384;
        #pragma unroll
        for (int ks = 0; ks < 4; ++ks) {
            uint32_t afh[4][4];
            #pragma unroll
            for (int mi = 0; mi < 4; ++mi) {
                int rowl = warp_m * 64 + mi * 16 + (lane & 15);
                int cidx = ks * 2 + (lane >> 4);
                ldm_x4(afh[mi], ahb + (uint32_t)(rowl * 128 + ((cidx ^ (rowl & 7)) << 4)));
            }
            uint32_t bfh[4][2];
            #pragma unroll
            for (int ni = 0; ni < 4; ++ni) {
                int nrow = warp_n * 32 + ni * 8 + (lane & 7);
                int cidx = ks * 2 + ((lane >> 3) & 1);
                ldm_x2(bfh[ni], bhb + (uint32_t)(nrow * 128 + ((cidx ^ (nrow & 7)) << 4)));
            }
            #pragma unroll
            for (int mi = 0; mi < 4; ++mi)
                #pragma unroll
                for (int ni = 0; ni < 4; ++ni)
                    mma16816(&acc[(mi * 4 + ni) * 4], afh[mi], bfh[ni]);
            if (split) {
                uint32_t afl[4][4];
                #pragma unroll
                for (int mi = 0; mi < 4; ++mi) {
                    int rowl = warp_m * 64 + mi * 16 + (lane & 15);
                    int cidx = ks * 2 + (lane >> 4);
                    ldm_x4(afl[mi], alb + (uint32_t)(rowl * 128 + ((cidx ^ (rowl & 7)) << 4)));
                }
                uint32_t bfl[4][2];
                #pragma unroll
                for (int ni = 0; ni < 4; ++ni) {
                    int nrow = warp_n * 32 + ni * 8 + (lane & 7);
                    int cidx = ks * 2 + ((lane >> 3) & 1);
                    ldm_x2(bfl[ni], blb + (uint32_t)(nrow * 128 + ((cidx ^ (nrow & 7)) << 4)));
                }
                #pragma unroll
                for (int mi = 0; mi < 4; ++mi)
                    #pragma unroll
                    for (int ni = 0; ni < 4; ++ni) {
                        float* cc = &acc[(mi * 4 + ni) * 4];
                        mma16816(cc, afl[mi], bfh[ni]);
                        mma16816(cc, afh[mi], bfl[ni]);
                    }
            }
        }
    }

    // epilogue
    #pragma unroll
    for (int mi = 0; mi < 4; ++mi) {
        #pragma unroll
        for (int ni = 0; ni < 4; ++ni) {
            int r = m0 + warp_m * 64 + mi * 16 + (lane >> 2);
            int c = n0 + warp_n * 32 + ni * 8 + (lane & 3) * 2;
            float ba = __ldg(&bias[c]), bb = __ldg(&bias[c + 1]);
            const float* cc = &acc[(mi * 4 + ni) * 4];
            if (z <= 1) {
                __half* C = (z == 0) ? g_teh : g_ieh;
                if (r < M)
                    *(__half2*)(C + (size_t)r * H + c) = __floats2half2_rn(cc[0] + ba, cc[1] + bb);
                if (r + 8 < M)
                    *(__half2*)(C + (size_t)(r + 8) * H + c) = __floats2half2_rn(cc[2] + ba, cc[3] + bb);
            } else {
                float* C = (z == 2) ? g_q : (z == 3) ? g_k : g_v;
                if (r < M)     *(float2*)(C + (size_t)r * H + c)       = make_float2(cc[0] + ba, cc[1] + bb);
                if (r + 8 < M) *(float2*)(C + (size_t)(r + 8) * H + c) = make_float2(cc[2] + ba, cc[3] + bb);
            }
        }
    }
}

// ============================================================================
// Gate kernel (R10 config): M=256 (16t x 16i), N=384 per pass (2 passes),
// K-chunk 32. 512 thr, 16 warps 2M x 8N, warp tile 128x48, fp16 acc.
// ============================================================================
#define GT_ZS   0
#define GT_B1   8192
#define GT_W2   11264
#define GT_TE   14336
#define GT_IE   39168
#define GT_A    64000
#define GT_B    96768
#define GT_SMEM 145920
#define TE_STR  776      // padded half stride

__device__ __forceinline__ void gt_fill_b(uint32_t sb, const __half* W1T,
                                          int gs, int tid) {
    const int n0 = (gs >= 24) ? 384 : 0;
    const int k0 = (gs >= 24 ? gs - 24 : gs) * 32;
    const uint32_t base = sb + GT_B + (gs & 1) * 24576;
    #pragma unroll
    for (int it = 0; it < 3; ++it) {
        int idx = tid + it * 512;          // 0..1535 (384 rows x 4 chunks)
        int r = idx >> 2, c = idx & 3;
        uint32_t dst = base + (uint32_t)(r * 64 + (((c + (r >> 1)) & 3) << 4));
        CPA(dst, W1T + (size_t)(n0 + r) * H + k0 + c * 8);
    }
    CPC();
}

__global__ __launch_bounds__(512)
void gate_kernel(const float* __restrict__ b1, const float* __restrict__ W2,
                 const float* __restrict__ b2) {
    extern __shared__ char smem[];
    const uint32_t sb = smem_u32(smem);
    const int tid = threadIdx.x;
    const int wid = tid >> 5, lane = tid & 31;
    const int warp_m = wid >> 3;        // 2 M-groups of 128 rows
    const int warp_n = wid & 7;         // 8 N-groups of 48 cols
    const int b  = blockIdx.z;
    const int t0 = blockIdx.y * 16;
    const int i0 = blockIdx.x * 16;

    float* zs  = (float*)(smem + GT_ZS);        // [8 warp_n][256 rows]
    float* b1s = (float*)(smem + GT_B1);
    float* w2s = (float*)(smem + GT_W2);
    __half* te = (__half*)(smem + GT_TE);
    __half* ie = (__half*)(smem + GT_IE);
    const __half* W1T = g_WTh + 5LL * H * H;

    // issue first B chunk immediately
    gt_fill_b(sb, W1T, 0, tid);

    for (int idx = tid; idx < 2048; idx += 512) zs[idx] = 0.f;
    for (int idx = tid; idx < H; idx += 512) { b1s[idx] = b1[idx]; w2s[idx] = W2[idx]; }

    // stage te/ie (already half in gmem; straight copy into padded stride)
    {
        const __half* teg = g_teh + ((size_t)b * TLEN + t0) * H;
        for (int u = tid; u < 16 * (H / 4); u += 512) {
            int r = u / (H / 4), c4 = (u % (H / 4)) * 4;
            *(uint2*)((char*)te + (r * TE_STR + c4) * 2) =
                *(const uint2*)(teg + r * H + c4);
        }
        const __half* ieg = g_ieh + (size_t)b * ILEN * H;
        for (int u = tid; u < 16 * (H / 4); u += 512) {
            int r = u / (H / 4), c4 = (u % (H / 4)) * 4;
            int gi = i0 + r;
            uint2 v = make_uint2(0u, 0u);
            if (gi < ILEN) v = *(const uint2*)(ieg + (size_t)gi * H + c4);
            *(uint2*)((char*)ie + (r * TE_STR + c4) * 2) = v;
        }
    }
    __syncthreads();

    for (int nc = 0; nc < 2; ++nc) {
        const int n0 = nc * 384;
        uint32_t hacc[96];                 // 8 mi x 6 ni x 2 b32
        #pragma unroll
        for (int q = 0; q < 96; ++q) hacc[q] = 0u;

        for (int kc = 0; kc < 24; ++kc) {
            const int gs = nc * 24 + kc;
            const int buf = gs & 1;
            const int k0 = kc * 32;

            // build A tile: rel = te*ie, 256 rows x 32 halves (64B rows)
            {
                char* ab = smem + GT_A + buf * 16384;
                #pragma unroll
                for (int it = 0; it < 2; ++it) {
                    int idx = tid + it * 512;     // 0..1023 (256 rows x 4 chunks)
                    int r = idx >> 2, c = idx & 3;
                    const __half* tp = te + (r >> 4) * TE_STR + k0 + c * 8;
                    const __half* ip = ie + (r & 15) * TE_STR + k0 + c * 8;
                    uint4 t4 = *(const uint4*)tp;
                    uint4 i4 = *(const uint4*)ip;
                    uint4 p;
                    p.x = hm2(t4.x, i4.x); p.y = hm2(t4.y, i4.y);
                    p.z = hm2(t4.z, i4.z); p.w = hm2(t4.w, i4.w);
                    *(uint4*)(ab + r * 64 + (((c + (r >> 1)) & 3) << 4)) = p;
                }
            }
            CPW0();
            __syncthreads();
            if (gs < 47) gt_fill_b(sb, W1T, gs + 1, tid);

            const uint32_t abase = sb + GT_A + buf * 16384;
            const uint32_t bbase = sb + GT_B + buf * 24576;
            #pragma unroll
            for (int ks = 0; ks < 2; ++ks) {
                uint32_t bf[3][4];
                #pragma unroll
                for (int nip = 0; nip < 3; ++nip) {
                    int g = lane >> 3;
                    int nrow = warp_n * 48 + nip * 16 + ((g >> 1) << 3) + (lane & 7);
                    int cidx = ks * 2 + (g & 1);
                    ldm_x4(bf[nip], bbase +
                        (uint32_t)(nrow * 64 + (((cidx + (nrow >> 1)) & 3) << 4)));
                }
                #pragma unroll
                for (int mi = 0; mi < 8; ++mi) {
                    uint32_t af[4];
                    int rowl = warp_m * 128 + mi * 16 + (lane & 15);
                    int cidx = ks * 2 + (lane >> 4);
                    ldm_x4(af, abase +
                        (uint32_t)(rowl * 64 + (((cidx + (rowl >> 1)) & 3) << 4)));
                    #pragma unroll
                    for (int nip = 0; nip < 3; ++nip) {
                        mma16816h(&hacc[(mi * 6 + nip * 2 + 0) * 2], af, &bf[nip][0]);
                        mma16816h(&hacc[(mi * 6 + nip * 2 + 1) * 2], af, &bf[nip][2]);
                    }
                }
            }
        }

        // N-pass epilogue: unpack fp16 acc, +b1, relu, dot W2 -> zs partials
        #pragma unroll
        for (int mi = 0; mi < 8; ++mi) {
            float z0 = 0.f, z1 = 0.f;
            #pragma unroll
            for (int ni = 0; ni < 6; ++ni) {
                int c = n0 + warp_n * 48 + ni * 8 + (lane & 3) * 2;
                float b1a = b1s[c], b1b = b1s[c + 1];
                float w2a = w2s[c], w2b = w2s[c + 1];
                const uint32_t* hc = &hacc[(mi * 6 + ni) * 2];
                float2 lo = h2f2(hc[0]);
                float2 hi = h2f2(hc[1]);
                z0 += fmaxf(lo.x + b1a, 0.f) * w2a + fmaxf(lo.y + b1b, 0.f) * w2b;
                z1 += fmaxf(hi.x + b1a, 0.f) * w2a + fmaxf(hi.y + b1b, 0.f) * w2b;
            }
            z0 += __shfl_xor_sync(0xffffffffu, z0, 1);
            z0 += __shfl_xor_sync(0xffffffffu, z0, 2);
            z1 += __shfl_xor_sync(0xffffffffu, z1, 1);
            z1 += __shfl_xor_sync(0xffffffffu, z1, 2);
            if ((lane & 3) == 0) {
                int r = warp_m * 128 + mi * 16 + (lane >> 2);
                zs[warp_n * 256 + r]     += z0;
                zs[warp_n * 256 + r + 8] += z1;
            }
        }
    }

    __syncthreads();
    if (tid < 256) {
        float z = b2[0];
        #pragma unroll
        for (int w = 0; w < 8; ++w) z += zs[w * 256 + tid];
        int t_l = tid >> 4, i_l = tid & 15;
        if (i0 + i_l < ILEN)
            g_gate[((size_t)b * TLEN + t0 + t_l) * ILEN + i0 + i_l] = 1.f / (1.f + expf(-z));
    }
}

// ---------------- repack k -> kT[b][h][d][i] ----------------
__global__ __launch_bounds__(256)
void repack_kT_kernel() {
    int idx = blockIdx.x * 256 + threadIdx.x;
    const int total = BSZ*NHEADS*DH*ILEN;
    if (idx >= total) return;
    int i = idx % ILEN;
    int d = (idx / ILEN) % DH;
    int h = (idx / (ILEN*DH)) % NHEADS;
    int b = idx / (ILEN*DH*NHEADS);
    g_kT[idx] = g_k[(b*ILEN + i)*H + h*DH + d];
}

// ---------------- attention: scores -> softmax -> *gate -> ctx ----------------
__global__ __launch_bounds__(256)
void attn_kernel(float* __restrict__ out) {
    __shared__ float q_s[8][DH];
    __shared__ float p_s[8][ILEN + 3];

    const int w    = threadIdx.x >> 5;
    const int lane = threadIdx.x & 31;
    const int b = blockIdx.z, h = blockIdx.y;
    const int t = blockIdx.x * 8 + w;

    const float* qrow = g_q + (b*TLEN + t)*H + h*DH;
    q_s[w][lane]      = qrow[lane];
    q_s[w][lane + 32] = qrow[lane + 32];
    __syncwarp();

    const float* kT = g_kT + (b*NHEADS + h) * DH * ILEN;
    const float scale = 0.125f;

    float mx = -1e30f;
    for (int c = 0; c < 7; ++c) {
        int i = c*32 + lane;
        float s = -1e30f;
        if (i < ILEN) {
            float a0 = 0.f, a1 = 0.f, a2 = 0.f, a3 = 0.f;
            #pragma unroll
            for (int d = 0; d < DH; d += 4) {
                a0 += q_s[w][d+0] * kT[(d+0)*ILEN + i];
                a1 += q_s[w][d+1] * kT[(d+1)*ILEN + i];
                a2 += q_s[w][d+2] * kT[(d+2)*ILEN + i];
                a3 += q_s[w][d+3] * kT[(d+3)*ILEN + i];
            }
            s = (a0 + a1 + a2 + a3) * scale;
            p_s[w][i] = s;
        }
        mx = fmaxf(mx, s);
    }
    #pragma unroll
    for (int off = 16; off; off >>= 1)
        mx = fmaxf(mx, __shfl_xor_sync(0xffffffffu, mx, off));

    float sm = 0.f;
    for (int c = 0; c < 7; ++c) {
        int i = c*32 + lane;
        if (i < ILEN) {
            float e = expf(p_s[w][i] - mx);
            p_s[w][i] = e;
            sm += e;
        }
    }
    #pragma unroll
    for (int off = 16; off; off >>= 1)
        sm += __shfl_xor_sync(0xffffffffu, sm, off);
    float inv = 1.f / sm;

    const float* gaterow = g_gate + (b*TLEN + t)*ILEN;
    for (int c = 0; c < 7; ++c) {
        int i = c*32 + lane;
        if (i < ILEN) p_s[w][i] *= inv * gaterow[i];
    }
    __syncwarp();

    float c0 = 0.f, c1 = 0.f;
    const float* vbase = g_v + b*ILEN*H + h*DH;
    for (int i = 0; i < ILEN; ++i) {
        float p = p_s[w][i];
        c0 += p * vbase[i*H + lane];
        c1 += p * vbase[i*H + lane + 32];
    }
    float* orow = out + (b*TLEN + t)*H + h*DH;
    orow[lane]      = c0;
    orow[lane + 32] = c1;
}

// ---------------- launch: two-stream overlap of q/k/v branch under gate ----
extern "C" void kernel_launch(void* const* d_in, const int* in_sizes, int n_in,
                              void* d_out, int out_size) {
    const float* text  = (const float*)d_in[0];
    const float* image = (const float*)d_in[1];
    const float* Wq = (const float*)d_in[2];  const float* bq = (const float*)d_in[3];
    const float* Wk = (const float*)d_in[4];  const float* bk = (const float*)d_in[5];
    const float* Wv = (const float*)d_in[6];  const float* bv = (const float*)d_in[7];
    const float* Wt = (const float*)d_in[8];  const float* bt = (const float*)d_in[9];
    const float* Wi = (const float*)d_in[10]; const float* bi = (const float*)d_in[11];
    const float* W1 = (const float*)d_in[12]; const float* b1 = (const float*)d_in[13];
    const float* W2 = (const float*)d_in[14]; const float* b2 = (const float*)d_in[15];
    float* out = (float*)d_out;

    cudaFuncSetAttribute(proj_all_kernel, cudaFuncAttributeMaxDynamicSharedMemorySize, PJ_SMEM);
    cudaFuncSetAttribute(gate_kernel,     cudaFuncAttributeMaxDynamicSharedMemorySize, GT_SMEM);

    cudaStream_t sb;
    cudaStreamCreateWithFlags(&sb, cudaStreamNonBlocking);
    cudaEvent_t e1, e2;
    cudaEventCreateWithFlags(&e1, cudaEventDisableTiming);
    cudaEventCreateWithFlags(&e2, cudaEventDisableTiming);

    // main stream: prep -> te/ie proj -> gate
    prep_weights<<<dim3(24, 24, 6), 256>>>(Wt, Wq, Wi, Wk, Wv, W1);
    cudaEventRecord(e1, 0);

    // side stream: q/k/v proj + repack, overlapped under gate
    cudaStreamWaitEvent(sb, e1, 0);
    proj_all_kernel<<<dim3(6, 13, 3), 256, PJ_SMEM, sb>>>(text, image, bt, bi, bq, bk, bv, 2);
    repack_kT_kernel<<<(BSZ*NHEADS*DH*ILEN + 255)/256, 256, 0, sb>>>();
    cudaEventRecord(e2, sb);

    proj_all_kernel<<<dim3(6, 13, 2), 256, PJ_SMEM>>>(text, image, bt, bi, bq, bk, bv, 0);
    gate_kernel<<<dim3(13, 4, 8), 512, GT_SMEM>>>(b1, W2, b2);

    // join and finish
    cudaStreamWaitEvent(0, e2, 0);
    attn_kernel<<<dim3(TLEN/8, NHEADS, BSZ), 256>>>(out);
}